// round 6
// baseline (speedup 1.0000x reference)
#include <cuda_runtime.h>
#include <math.h>
#include <stdint.h>

// ---------------------------------------------------------------------------
// TransformerBlock: mma.sync tf32 GEMMs (3-stage cp.async pipeline,
// pre-rounded operands) + tf32 flash attention
// Shapes: B=4, T=2048 (BT=8192), C=1024, H=16, D=64, DFF=4096
// ---------------------------------------------------------------------------

#define BT   8192
#define C    1024
#define C3   3072
#define H    16
#define D    64
#define DFF  4096
#define T    2048
#define EPS  1e-5f

// Scratch (__device__ globals; no allocations allowed)
__device__ float g_ln[BT * C];
__device__ float g_qkv[BT * C3];
__device__ float g_attn[BT * C];
__device__ float g_h1[BT * DFF];
// tf32-rounded weight copies
#define WT_QKV  0
#define WT_PROJ (WT_QKV + C * C3)
#define WT_W1   (WT_PROJ + C * C)
#define WT_W2   (WT_W1 + C * DFF)
#define WT_TOT  (WT_W2 + DFF * C)
__device__ float g_wt[WT_TOT];

// ---------------------------------------------------------------------------
// Helpers
// ---------------------------------------------------------------------------
__device__ __forceinline__ uint32_t smem_u32(const void* p) {
    uint32_t a;
    asm("{ .reg .u64 t; cvta.to.shared.u64 t, %1; cvt.u32.u64 %0, t; }" : "=r"(a) : "l"(p));
    return a;
}
__device__ __forceinline__ void cp_async16(uint32_t dst, const void* src) {
    asm volatile("cp.async.ca.shared.global [%0], [%1], 16;" :: "r"(dst), "l"(src) : "memory");
}
__device__ __forceinline__ void cp_commit() {
    asm volatile("cp.async.commit_group;" ::: "memory");
}
template<int N>
__device__ __forceinline__ void cp_wait() {
    asm volatile("cp.async.wait_group %0;" :: "n"(N) : "memory");
}
__device__ __forceinline__ uint32_t cvt_tf32(float x) {
    uint32_t u;
    asm("cvt.rna.tf32.f32 %0, %1;" : "=r"(u) : "f"(x));
    return u;
}
__device__ __forceinline__ float cvtf_tf32(float x) {
    return __uint_as_float(cvt_tf32(x));
}
__device__ __forceinline__ void mma_16n8k8(float* d, const uint32_t* a, const uint32_t* b) {
    asm volatile(
        "mma.sync.aligned.m16n8k8.row.col.f32.tf32.tf32.f32 "
        "{%0,%1,%2,%3}, {%4,%5,%6,%7}, {%8,%9}, {%0,%1,%2,%3};"
        : "+f"(d[0]), "+f"(d[1]), "+f"(d[2]), "+f"(d[3])
        : "r"(a[0]), "r"(a[1]), "r"(a[2]), "r"(a[3]), "r"(b[0]), "r"(b[1]));
}
__device__ __forceinline__ float gelu_exact(float v) {
    return 0.5f * v * (1.0f + erff(v * 0.70710678118654752f));
}

// ---------------------------------------------------------------------------
// Weight convert: elementwise tf32 round
// ---------------------------------------------------------------------------
__global__ __launch_bounds__(256) void wcvt_kernel(
    const float* __restrict__ src, float* __restrict__ dst, int n4)
{
    int i = blockIdx.x * 256 + threadIdx.x;
    int stride = gridDim.x * 256;
    for (; i < n4; i += stride) {
        float4 v = *(const float4*)(src + i * 4);
        v.x = cvtf_tf32(v.x); v.y = cvtf_tf32(v.y);
        v.z = cvtf_tf32(v.z); v.w = cvtf_tf32(v.w);
        *(float4*)(dst + i * 4) = v;
    }
}

// ---------------------------------------------------------------------------
// LayerNorm (output tf32-rounded; sole consumer is a GEMM)
// ---------------------------------------------------------------------------
__global__ __launch_bounds__(256) void ln_kernel(
    const float* __restrict__ x, const float* __restrict__ g,
    const float* __restrict__ beta, float* __restrict__ out)
{
    int row = blockIdx.x;
    int t = threadIdx.x;
    const float* xr = x + (size_t)row * C;
    float4 xv = *(const float4*)(xr + t * 4);
    float s  = xv.x + xv.y + xv.z + xv.w;
    float s2 = xv.x * xv.x + xv.y * xv.y + xv.z * xv.z + xv.w * xv.w;
    #pragma unroll
    for (int o = 16; o > 0; o >>= 1) {
        s  += __shfl_xor_sync(0xffffffffu, s,  o);
        s2 += __shfl_xor_sync(0xffffffffu, s2, o);
    }
    __shared__ float ss[8], ss2[8];
    int w = t >> 5, lane = t & 31;
    if (lane == 0) { ss[w] = s; ss2[w] = s2; }
    __syncthreads();
    if (w == 0) {
        s  = (lane < 8) ? ss[lane]  : 0.f;
        s2 = (lane < 8) ? ss2[lane] : 0.f;
        #pragma unroll
        for (int o = 4; o > 0; o >>= 1) {
            s  += __shfl_xor_sync(0xffffffffu, s,  o);
            s2 += __shfl_xor_sync(0xffffffffu, s2, o);
        }
        if (lane == 0) { ss[0] = s; ss2[0] = s2; }
    }
    __syncthreads();
    float mu  = ss[0] * (1.0f / C);
    float var = ss2[0] * (1.0f / C) - mu * mu;
    float inv = rsqrtf(var + EPS);
    float4 gv = *(const float4*)(g + t * 4);
    float4 bv = *(const float4*)(beta + t * 4);
    float4 ov;
    ov.x = cvtf_tf32((xv.x - mu) * inv * gv.x + bv.x);
    ov.y = cvtf_tf32((xv.y - mu) * inv * gv.y + bv.y);
    ov.z = cvtf_tf32((xv.z - mu) * inv * gv.z + bv.z);
    ov.w = cvtf_tf32((xv.w - mu) * inv * gv.w + bv.w);
    *(float4*)(out + (size_t)row * C + t * 4) = ov;
}

// ---------------------------------------------------------------------------
// tf32 mma.sync GEMM: 128x128 CTA tile, K-chunk 32, THREE-stage cp.async.
// Operands pre-rounded to tf32 -> no cvt in inner loop.
// ---------------------------------------------------------------------------
#define A_STRIDE 36
#define B_STRIDE 132
#define ASZ (128 * A_STRIDE)
#define BSZ (32 * B_STRIDE)
#define NSTAGE 3
#define GEMM_SMEM_BYTES (NSTAGE * (ASZ + BSZ) * 4)

template<int ACT, bool BIAS, bool RESID, bool ROUND_OUT>
__global__ __launch_bounds__(256, 2) void gemm_mma(
    const float* __restrict__ A, const float* __restrict__ B,
    const float* __restrict__ bias, const float* __restrict__ resid,
    float* __restrict__ Cout, int M, int N, int K)
{
    extern __shared__ float smem[];
    // layout: [stage][A(ASZ) | B(BSZ)]
    int t    = threadIdx.x;
    int lane = t & 31;
    int w    = t >> 5;
    int grp  = lane >> 2;
    int tg   = lane & 3;
    int bm = blockIdx.y * 128;
    int bn = blockIdx.x * 128;
    int wm = (w >> 2) * 64;
    int wn = (w & 3) * 32;

    float acc[4][4][4];
    #pragma unroll
    for (int mi = 0; mi < 4; mi++)
        #pragma unroll
        for (int ni = 0; ni < 4; ni++)
            #pragma unroll
            for (int r = 0; r < 4; r++) acc[mi][ni][r] = 0.f;

    const int NCH = K >> 5;

    auto load_chunk = [&](int c) {
        int buf = c % NSTAGE;
        float* As = smem + buf * (ASZ + BSZ);
        float* Bs = As + ASZ;
        uint32_t aBase = smem_u32(As);
        uint32_t bBase = smem_u32(Bs);
        int k0 = c << 5;
        #pragma unroll
        for (int it = 0; it < 4; it++) {
            int idx  = t + it * 256;
            int row  = idx >> 3;
            int col4 = (idx & 7) << 2;
            cp_async16(aBase + (uint32_t)(row * A_STRIDE + col4) * 4,
                       A + (size_t)(bm + row) * K + k0 + col4);
        }
        #pragma unroll
        for (int it = 0; it < 4; it++) {
            int idx  = t + it * 256;
            int row  = idx >> 5;
            int col4 = (idx & 31) << 2;
            cp_async16(bBase + (uint32_t)(row * B_STRIDE + col4) * 4,
                       B + (size_t)(k0 + row) * N + bn + col4);
        }
        cp_commit();
    };

    load_chunk(0);
    load_chunk(1);

    for (int c = 0; c < NCH; c++) {
        if (c + 2 < NCH) { load_chunk(c + 2); cp_wait<2>(); }
        else if (c + 1 < NCH) { cp_wait<1>(); }
        else { cp_wait<0>(); }
        __syncthreads();

        int buf = c % NSTAGE;
        const float* Asb = smem + buf * (ASZ + BSZ);
        const float* Bsb = Asb + ASZ;

        #pragma unroll
        for (int ks = 0; ks < 4; ks++) {
            int k = ks << 3;
            uint32_t af[4][4], bf[4][2];
            #pragma unroll
            for (int mi = 0; mi < 4; mi++) {
                const float* ap = Asb + (wm + mi * 16 + grp) * A_STRIDE + k + tg;
                af[mi][0] = __float_as_uint(ap[0]);
                af[mi][1] = __float_as_uint(ap[8 * A_STRIDE]);
                af[mi][2] = __float_as_uint(ap[4]);
                af[mi][3] = __float_as_uint(ap[8 * A_STRIDE + 4]);
            }
            #pragma unroll
            for (int ni = 0; ni < 4; ni++) {
                const float* bp = Bsb + (k + tg) * B_STRIDE + wn + ni * 8 + grp;
                bf[ni][0] = __float_as_uint(bp[0]);
                bf[ni][1] = __float_as_uint(bp[4 * B_STRIDE]);
            }
            #pragma unroll
            for (int mi = 0; mi < 4; mi++)
                #pragma unroll
                for (int ni = 0; ni < 4; ni++)
                    mma_16n8k8(acc[mi][ni], af[mi], bf[ni]);
        }
        __syncthreads();
    }

    #pragma unroll
    for (int mi = 0; mi < 4; mi++) {
        #pragma unroll
        for (int half = 0; half < 2; half++) {
            int row = bm + wm + mi * 16 + grp + half * 8;
            float* orow = Cout + (size_t)row * N + bn;
            const float* rrow = RESID ? (resid + (size_t)row * N + bn) : nullptr;
            #pragma unroll
            for (int ni = 0; ni < 4; ni++) {
                int col = wn + ni * 8 + tg * 2;
                float v0 = acc[mi][ni][half * 2 + 0];
                float v1 = acc[mi][ni][half * 2 + 1];
                if (BIAS) {
                    float2 bb = *(const float2*)(bias + bn + col);
                    v0 += bb.x; v1 += bb.y;
                }
                if (ACT == 1) { v0 = gelu_exact(v0); v1 = gelu_exact(v1); }
                if (RESID) {
                    float2 rr = *(const float2*)(rrow + col);
                    v0 += rr.x; v1 += rr.y;
                }
                if (ROUND_OUT) { v0 = cvtf_tf32(v0); v1 = cvtf_tf32(v1); }
                *(float2*)(orow + col) = make_float2(v0, v1);
            }
        }
    }
}

// ---------------------------------------------------------------------------
// Flash attention, mma.sync tf32 (qkv pre-rounded tf32)
// ---------------------------------------------------------------------------
#define ATT_STR 72
#define ATTN_SMEM_BYTES ((128 + 64 + 64 + 128) * ATT_STR * 4)

__global__ __launch_bounds__(128, 2) void attn_mma_kernel(
    const float* __restrict__ qkv, float* __restrict__ out)
{
    extern __shared__ float sm[];
    float* Qs = sm;
    float* Ks = Qs + 128 * ATT_STR;
    float* Vt = Ks + 64 * ATT_STR;
    float* Ps = Vt + 64 * ATT_STR;

    int qt = blockIdx.x, h = blockIdx.y, b = blockIdx.z;
    int t = threadIdx.x, lane = t & 31, w = t >> 5;
    int grp = lane >> 2, tg = lane & 3;

    const size_t tok0 = (size_t)b * T;

    #pragma unroll
    for (int it = 0; it < 16; it++) {
        int idx = t + it * 128;
        int row = idx >> 4;
        int c4  = (idx & 15) << 2;
        const float* p = qkv + (tok0 + qt * 128 + row) * C3 + h * D + c4;
        float4 v = *(const float4*)p;
        int base = c4 & ~7;
        int off  = (c4 & 4) ? 1 : 0;
        float* qr = Qs + row * ATT_STR + base + off;
        qr[0] = v.x * 0.125f;
        qr[2] = v.y * 0.125f;
        qr[4] = v.z * 0.125f;
        qr[6] = v.w * 0.125f;
    }

    float m[2][2], l[2][2];
    float oacc[2][8][4];
    #pragma unroll
    for (int mi = 0; mi < 2; mi++) {
        m[mi][0] = m[mi][1] = -1e30f;
        l[mi][0] = l[mi][1] = 0.f;
        #pragma unroll
        for (int nt = 0; nt < 8; nt++)
            #pragma unroll
            for (int r = 0; r < 4; r++) oacc[mi][nt][r] = 0.f;
    }

    int vkey  = t & 63;
    int vhalf = t >> 6;
    int pckey = (vkey & ~7) | (((vkey & 3) << 1) | ((vkey >> 2) & 1));
    int pc0 = (((tg * 2) & 3) << 1) | (((tg * 2) >> 2) & 1);
    int pc1 = (((tg * 2 + 1) & 3) << 1) | (((tg * 2 + 1) >> 2) & 1);

    float* PsW = Ps + w * 32 * ATT_STR;

    for (int kt = 0; kt < T; kt += 64) {
        __syncthreads();

        #pragma unroll
        for (int it = 0; it < 8; it++) {
            int idx = t + it * 128;
            int row = idx >> 4;
            int c4  = (idx & 15) << 2;
            const float* p = qkv + (tok0 + kt + row) * C3 + C + h * D + c4;
            float4 v = *(const float4*)p;
            int base = c4 & ~7;
            int off  = (c4 & 4) ? 1 : 0;
            float* kr = Ks + row * ATT_STR + base + off;
            kr[0] = v.x;
            kr[2] = v.y;
            kr[4] = v.z;
            kr[6] = v.w;
        }
        {
            const float* vp = qkv + (tok0 + kt + vkey) * C3 + 2 * C + h * D + vhalf * 32;
            #pragma unroll
            for (int j4 = 0; j4 < 8; j4++) {
                float4 v = *(const float4*)(vp + j4 * 4);
                int d = vhalf * 32 + j4 * 4;
                Vt[(d + 0) * ATT_STR + pckey] = v.x;
                Vt[(d + 1) * ATT_STR + pckey] = v.y;
                Vt[(d + 2) * ATT_STR + pckey] = v.z;
                Vt[(d + 3) * ATT_STR + pckey] = v.w;
            }
        }
        __syncthreads();

        float sacc[2][8][4];
        #pragma unroll
        for (int mi = 0; mi < 2; mi++)
            #pragma unroll
            for (int nt = 0; nt < 8; nt++)
                #pragma unroll
                for (int r = 0; r < 4; r++) sacc[mi][nt][r] = 0.f;

        #pragma unroll
        for (int ks = 0; ks < 8; ks++) {
            uint32_t a[2][4];
            #pragma unroll
            for (int mi = 0; mi < 2; mi++) {
                const float2 lo = *(const float2*)(Qs + (w * 32 + mi * 16 + grp)     * ATT_STR + ks * 8 + tg * 2);
                const float2 hi = *(const float2*)(Qs + (w * 32 + mi * 16 + grp + 8) * ATT_STR + ks * 8 + tg * 2);
                a[mi][0] = __float_as_uint(lo.x);
                a[mi][1] = __float_as_uint(hi.x);
                a[mi][2] = __float_as_uint(lo.y);
                a[mi][3] = __float_as_uint(hi.y);
            }
            #pragma unroll
            for (int nt = 0; nt < 8; nt++) {
                const float2 bb = *(const float2*)(Ks + (nt * 8 + grp) * ATT_STR + ks * 8 + tg * 2);
                uint32_t bfr[2] = { __float_as_uint(bb.x), __float_as_uint(bb.y) };
                mma_16n8k8(sacc[0][nt], a[0], bfr);
                mma_16n8k8(sacc[1][nt], a[1], bfr);
            }
        }

        #pragma unroll
        for (int mi = 0; mi < 2; mi++) {
            float r0 = -1e30f, r1 = -1e30f;
            #pragma unroll
            for (int nt = 0; nt < 8; nt++) {
                r0 = fmaxf(r0, fmaxf(sacc[mi][nt][0], sacc[mi][nt][1]));
                r1 = fmaxf(r1, fmaxf(sacc[mi][nt][2], sacc[mi][nt][3]));
            }
            r0 = fmaxf(r0, __shfl_xor_sync(0xffffffffu, r0, 1));
            r0 = fmaxf(r0, __shfl_xor_sync(0xffffffffu, r0, 2));
            r1 = fmaxf(r1, __shfl_xor_sync(0xffffffffu, r1, 1));
            r1 = fmaxf(r1, __shfl_xor_sync(0xffffffffu, r1, 2));
            float mn0 = fmaxf(m[mi][0], r0);
            float mn1 = fmaxf(m[mi][1], r1);
            float c0 = __expf(m[mi][0] - mn0);
            float c1 = __expf(m[mi][1] - mn1);
            m[mi][0] = mn0; m[mi][1] = mn1;
            l[mi][0] *= c0; l[mi][1] *= c1;
            #pragma unroll
            for (int nt = 0; nt < 8; nt++) {
                oacc[mi][nt][0] *= c0; oacc[mi][nt][1] *= c0;
                oacc[mi][nt][2] *= c1; oacc[mi][nt][3] *= c1;
            }
            float* plo = PsW + (mi * 16 + grp)     * ATT_STR;
            float* phi = PsW + (mi * 16 + grp + 8) * ATT_STR;
            #pragma unroll
            for (int nt = 0; nt < 8; nt++) {
                float p0 = __expf(sacc[mi][nt][0] - mn0);
                float p1 = __expf(sacc[mi][nt][1] - mn0);
                float p2 = __expf(sacc[mi][nt][2] - mn1);
                float p3 = __expf(sacc[mi][nt][3] - mn1);
                l[mi][0] += p0 + p1;
                l[mi][1] += p2 + p3;
                plo[nt * 8 + pc0] = cvtf_tf32(p0);
                plo[nt * 8 + pc1] = cvtf_tf32(p1);
                phi[nt * 8 + pc0] = cvtf_tf32(p2);
                phi[nt * 8 + pc1] = cvtf_tf32(p3);
            }
        }
        __syncwarp();

        #pragma unroll
        for (int ks = 0; ks < 8; ks++) {
            uint32_t a[2][4];
            #pragma unroll
            for (int mi = 0; mi < 2; mi++) {
                const float2 lo = *(const float2*)(PsW + (mi * 16 + grp)     * ATT_STR + ks * 8 + tg * 2);
                const float2 hi = *(const float2*)(PsW + (mi * 16 + grp + 8) * ATT_STR + ks * 8 + tg * 2);
                a[mi][0] = __float_as_uint(lo.x);
                a[mi][1] = __float_as_uint(hi.x);
                a[mi][2] = __float_as_uint(lo.y);
                a[mi][3] = __float_as_uint(hi.y);
            }
            #pragma unroll
            for (int nt = 0; nt < 8; nt++) {
                const float2 bb = *(const float2*)(Vt + (nt * 8 + grp) * ATT_STR + ks * 8 + tg * 2);
                uint32_t bfr[2] = { __float_as_uint(bb.x), __float_as_uint(bb.y) };
                mma_16n8k8(oacc[0][nt], a[0], bfr);
                mma_16n8k8(oacc[1][nt], a[1], bfr);
            }
        }
    }

    #pragma unroll
    for (int mi = 0; mi < 2; mi++) {
        float l0 = l[mi][0], l1 = l[mi][1];
        l0 += __shfl_xor_sync(0xffffffffu, l0, 1);
        l0 += __shfl_xor_sync(0xffffffffu, l0, 2);
        l1 += __shfl_xor_sync(0xffffffffu, l1, 1);
        l1 += __shfl_xor_sync(0xffffffffu, l1, 2);
        float i0 = 1.f / l0, i1 = 1.f / l1;
        int rlo = qt * 128 + w * 32 + mi * 16 + grp;
        float* olo = out + (tok0 + rlo) * C + h * D;
        float* ohi = out + (tok0 + rlo + 8) * C + h * D;
        #pragma unroll
        for (int nt = 0; nt < 8; nt++) {
            int col = nt * 8 + tg * 2;
            *(float2*)(olo + col) = make_float2(cvtf_tf32(oacc[mi][nt][0] * i0),
                                                cvtf_tf32(oacc[mi][nt][1] * i0));
            *(float2*)(ohi + col) = make_float2(cvtf_tf32(oacc[mi][nt][2] * i1),
                                                cvtf_tf32(oacc[mi][nt][3] * i1));
        }
    }
}

// ---------------------------------------------------------------------------
// Launch
// ---------------------------------------------------------------------------
extern "C" void kernel_launch(void* const* d_in, const int* in_sizes, int n_in,
                              void* d_out, int out_size)
{
    const float* x      = (const float*)d_in[0];
    const float* ln1_g  = (const float*)d_in[1];
    const float* ln1_b  = (const float*)d_in[2];
    const float* ln2_g  = (const float*)d_in[3];
    const float* ln2_b  = (const float*)d_in[4];
    const float* w_qkv  = (const float*)d_in[5];
    const float* w_proj = (const float*)d_in[6];
    const float* w1     = (const float*)d_in[7];
    const float* b1     = (const float*)d_in[8];
    const float* w2     = (const float*)d_in[9];
    const float* b2     = (const float*)d_in[10];
    float* out = (float*)d_out;

    float* ln   = nullptr;  cudaGetSymbolAddress((void**)&ln,   g_ln);
    float* qkv  = nullptr;  cudaGetSymbolAddress((void**)&qkv,  g_qkv);
    float* attn = nullptr;  cudaGetSymbolAddress((void**)&attn, g_attn);
    float* h1   = nullptr;  cudaGetSymbolAddress((void**)&h1,   g_h1);
    float* wt   = nullptr;  cudaGetSymbolAddress((void**)&wt,   g_wt);

    cudaFuncSetAttribute(gemm_mma<0, false, false, true >, cudaFuncAttributeMaxDynamicSharedMemorySize, GEMM_SMEM_BYTES);
    cudaFuncSetAttribute(gemm_mma<0, false, true,  false>, cudaFuncAttributeMaxDynamicSharedMemorySize, GEMM_SMEM_BYTES);
    cudaFuncSetAttribute(gemm_mma<1, true,  false, true >, cudaFuncAttributeMaxDynamicSharedMemorySize, GEMM_SMEM_BYTES);
    cudaFuncSetAttribute(gemm_mma<0, true,  true,  false>, cudaFuncAttributeMaxDynamicSharedMemorySize, GEMM_SMEM_BYTES);
    cudaFuncSetAttribute(attn_mma_kernel, cudaFuncAttributeMaxDynamicSharedMemorySize, ATTN_SMEM_BYTES);

    // 0) round weights to tf32 into scratch
    wcvt_kernel<<<2048, 256>>>(w_qkv,  wt + WT_QKV,  C * C3  / 4);
    wcvt_kernel<<<1024, 256>>>(w_proj, wt + WT_PROJ, C * C   / 4);
    wcvt_kernel<<<2048, 256>>>(w1,     wt + WT_W1,   C * DFF / 4);
    wcvt_kernel<<<2048, 256>>>(w2,     wt + WT_W2,   DFF * C / 4);

    // 1) LN1(x) -> ln (tf32-rounded)
    ln_kernel<<<BT, 256>>>(x, ln1_g, ln1_b, ln);

    // 2) qkv = ln @ w_qkv (output rounded; feeds attention MMAs)
    gemm_mma<0, false, false, true><<<dim3(C3 / 128, BT / 128), 256, GEMM_SMEM_BYTES>>>(
        ln, wt + WT_QKV, nullptr, nullptr, qkv, BT, C3, C);

    // 3) attention (tensor cores; output rounded)
    attn_mma_kernel<<<dim3(T / 128, H, 4), 128, ATTN_SMEM_BYTES>>>(qkv, attn);

    // 4) out = x + attn @ w_proj (fp32 residual, NOT rounded)
    gemm_mma<0, false, true, false><<<dim3(C / 128, BT / 128), 256, GEMM_SMEM_BYTES>>>(
        attn, wt + WT_PROJ, nullptr, x, out, BT, C, C);

    // 5) LN2(out) -> ln (tf32-rounded)
    ln_kernel<<<BT, 256>>>(out, ln2_g, ln2_b, ln);

    // 6) h1 = gelu(ln @ w1 + b1) (output rounded; feeds final GEMM)
    gemm_mma<1, true, false, true><<<dim3(DFF / 128, BT / 128), 256, GEMM_SMEM_BYTES>>>(
        ln, wt + WT_W1, b1, nullptr, h1, BT, DFF, C);

    // 7) out = out + h1 @ w2 + b2 (fp32, NOT rounded)
    gemm_mma<0, true, true, false><<<dim3(C / 128, BT / 128), 256, GEMM_SMEM_BYTES>>>(
        h1, wt + WT_W2, b2, out, out, BT, C, DFF);
}

// round 7
// speedup vs baseline: 1.2202x; 1.2202x over previous
#include <cuda_runtime.h>
#include <math.h>
#include <stdint.h>

// ---------------------------------------------------------------------------
// TransformerBlock: mma.sync tf32 GEMMs (ldmatrix fragments, B pre-transposed,
// 2-stage cp.async) + tf32 flash attention
// Shapes: B=4, T=2048 (BT=8192), C=1024, H=16, D=64, DFF=4096
// ---------------------------------------------------------------------------

#define BT   8192
#define C    1024
#define C3   3072
#define H    16
#define D    64
#define DFF  4096
#define T    2048
#define EPS  1e-5f

// Scratch (__device__ globals; no allocations allowed)
__device__ float g_ln[BT * C];
__device__ float g_qkv[BT * C3];
__device__ float g_attn[BT * C];
__device__ float g_h1[BT * DFF];
// tf32-rounded TRANSPOSED weights: [N][K] layout
#define WT_QKV  0
#define WT_PROJ (WT_QKV + C * C3)
#define WT_W1   (WT_PROJ + C * C)
#define WT_W2   (WT_W1 + C * DFF)
#define WT_TOT  (WT_W2 + DFF * C)
__device__ float g_wt[WT_TOT];

// ---------------------------------------------------------------------------
// Helpers
// ---------------------------------------------------------------------------
__device__ __forceinline__ uint32_t smem_u32(const void* p) {
    uint32_t a;
    asm("{ .reg .u64 t; cvta.to.shared.u64 t, %1; cvt.u32.u64 %0, t; }" : "=r"(a) : "l"(p));
    return a;
}
__device__ __forceinline__ void cp_async16(uint32_t dst, const void* src) {
    asm volatile("cp.async.ca.shared.global [%0], [%1], 16;" :: "r"(dst), "l"(src) : "memory");
}
__device__ __forceinline__ void cp_commit() {
    asm volatile("cp.async.commit_group;" ::: "memory");
}
template<int N>
__device__ __forceinline__ void cp_wait() {
    asm volatile("cp.async.wait_group %0;" :: "n"(N) : "memory");
}
__device__ __forceinline__ uint32_t cvt_tf32(float x) {
    uint32_t u;
    asm("cvt.rna.tf32.f32 %0, %1;" : "=r"(u) : "f"(x));
    return u;
}
__device__ __forceinline__ float cvtf_tf32(float x) {
    return __uint_as_float(cvt_tf32(x));
}
__device__ __forceinline__ void ldsm_x4(uint32_t& r0, uint32_t& r1, uint32_t& r2, uint32_t& r3,
                                        uint32_t addr) {
    asm volatile("ldmatrix.sync.aligned.m8n8.x4.shared.b16 {%0,%1,%2,%3}, [%4];"
                 : "=r"(r0), "=r"(r1), "=r"(r2), "=r"(r3) : "r"(addr));
}
__device__ __forceinline__ void mma_16n8k8(float* d, const uint32_t* a, const uint32_t* b) {
    asm volatile(
        "mma.sync.aligned.m16n8k8.row.col.f32.tf32.tf32.f32 "
        "{%0,%1,%2,%3}, {%4,%5,%6,%7}, {%8,%9}, {%0,%1,%2,%3};"
        : "+f"(d[0]), "+f"(d[1]), "+f"(d[2]), "+f"(d[3])
        : "r"(a[0]), "r"(a[1]), "r"(a[2]), "r"(a[3]), "r"(b[0]), "r"(b[1]));
}
__device__ __forceinline__ float gelu_exact(float v) {
    return 0.5f * v * (1.0f + erff(v * 0.70710678118654752f));
}

// ---------------------------------------------------------------------------
// Weight transpose + tf32 round: in [K][N] -> out [N][K]
// ---------------------------------------------------------------------------
__global__ __launch_bounds__(256) void wtr_kernel(
    const float* __restrict__ in, float* __restrict__ out, int K, int N)
{
    __shared__ float tile[32][33];
    int n0 = blockIdx.x * 32, k0 = blockIdx.y * 32;
    int tx = threadIdx.x, ty = threadIdx.y;
    #pragma unroll
    for (int i = ty; i < 32; i += 8)
        tile[i][tx] = in[(size_t)(k0 + i) * N + n0 + tx];
    __syncthreads();
    #pragma unroll
    for (int i = ty; i < 32; i += 8)
        out[(size_t)(n0 + i) * K + k0 + tx] = cvtf_tf32(tile[tx][i]);
}

// ---------------------------------------------------------------------------
// LayerNorm (output tf32-rounded; sole consumer is a GEMM)
// ---------------------------------------------------------------------------
__global__ __launch_bounds__(256) void ln_kernel(
    const float* __restrict__ x, const float* __restrict__ g,
    const float* __restrict__ beta, float* __restrict__ out)
{
    int row = blockIdx.x;
    int t = threadIdx.x;
    const float* xr = x + (size_t)row * C;
    float4 xv = *(const float4*)(xr + t * 4);
    float s  = xv.x + xv.y + xv.z + xv.w;
    float s2 = xv.x * xv.x + xv.y * xv.y + xv.z * xv.z + xv.w * xv.w;
    #pragma unroll
    for (int o = 16; o > 0; o >>= 1) {
        s  += __shfl_xor_sync(0xffffffffu, s,  o);
        s2 += __shfl_xor_sync(0xffffffffu, s2, o);
    }
    __shared__ float ss[8], ss2[8];
    int w = t >> 5, lane = t & 31;
    if (lane == 0) { ss[w] = s; ss2[w] = s2; }
    __syncthreads();
    if (w == 0) {
        s  = (lane < 8) ? ss[lane]  : 0.f;
        s2 = (lane < 8) ? ss2[lane] : 0.f;
        #pragma unroll
        for (int o = 4; o > 0; o >>= 1) {
            s  += __shfl_xor_sync(0xffffffffu, s,  o);
            s2 += __shfl_xor_sync(0xffffffffu, s2, o);
        }
        if (lane == 0) { ss[0] = s; ss2[0] = s2; }
    }
    __syncthreads();
    float mu  = ss[0] * (1.0f / C);
    float var = ss2[0] * (1.0f / C) - mu * mu;
    float inv = rsqrtf(var + EPS);
    float4 gv = *(const float4*)(g + t * 4);
    float4 bv = *(const float4*)(beta + t * 4);
    float4 ov;
    ov.x = cvtf_tf32((xv.x - mu) * inv * gv.x + bv.x);
    ov.y = cvtf_tf32((xv.y - mu) * inv * gv.y + bv.y);
    ov.z = cvtf_tf32((xv.z - mu) * inv * gv.z + bv.z);
    ov.w = cvtf_tf32((xv.w - mu) * inv * gv.w + bv.w);
    *(float4*)(out + (size_t)row * C + t * 4) = ov;
}

// ---------------------------------------------------------------------------
// tf32 mma.sync GEMM: D[M,N] = A[M,K] @ Bt[N,K]^T (+bias)(gelu)(+resid)
// CTA 128x128, K-chunk 32, 2-stage cp.async, ldmatrix fragment loads.
// Smem: A [128][36], Bt [128][36] per stage (stride 36 floats = 144B:
// 16B-aligned rows, conflict-free ldmatrix phases).
// ---------------------------------------------------------------------------
#define GSTR 36
#define TSZ (128 * GSTR)
#define NSTAGE 2
#define GEMM_SMEM_BYTES (NSTAGE * 2 * TSZ * 4)

template<int ACT, bool BIAS, bool RESID, bool ROUND_OUT>
__global__ __launch_bounds__(256, 2) void gemm_mma(
    const float* __restrict__ A, const float* __restrict__ Bt,
    const float* __restrict__ bias, const float* __restrict__ resid,
    float* __restrict__ Cout, int M, int N, int K)
{
    extern __shared__ float smem[];
    // layout: [stage][ A(TSZ) | B(TSZ) ]
    int t    = threadIdx.x;
    int lane = t & 31;
    int w    = t >> 5;
    int grp  = lane >> 2;
    int tg   = lane & 3;
    int bm = blockIdx.y * 128;
    int bn = blockIdx.x * 128;
    int wm = (w >> 2) * 64;
    int wn = (w & 3) * 32;

    uint32_t smemBase = smem_u32(smem);

    // ldmatrix per-lane offsets (bytes), tile index lsel = lane>>3
    int lrow = lane & 7;
    int lsel = lane >> 3;
    // A: tiles (rows lo/hi) x (k lo/hi): row += (lsel&1)*8, col += (lsel>>1)*4
    uint32_t a_off = (uint32_t)(((wm + lrow + (lsel & 1) * 8) * GSTR + (lsel >> 1) * 4) * 4);
    // B: tiles (n lo/hi) x (k lo/hi): n += (lsel>>1)*8, col += (lsel&1)*4
    uint32_t b_off = (uint32_t)(((wn + lrow + (lsel >> 1) * 8) * GSTR + (lsel & 1) * 4) * 4)
                   + (uint32_t)(TSZ * 4);

    float acc[4][4][4];
    #pragma unroll
    for (int mi = 0; mi < 4; mi++)
        #pragma unroll
        for (int ni = 0; ni < 4; ni++)
            #pragma unroll
            for (int r = 0; r < 4; r++) acc[mi][ni][r] = 0.f;

    const int NCH = K >> 5;

    auto load_chunk = [&](int c) {
        int buf = c & 1;
        uint32_t base = smemBase + (uint32_t)(buf * 2 * TSZ * 4);
        int k0 = c << 5;
        #pragma unroll
        for (int it = 0; it < 4; it++) {
            int idx  = t + it * 256;
            int row  = idx >> 3;
            int col4 = (idx & 7) << 2;
            uint32_t soff = (uint32_t)((row * GSTR + col4) * 4);
            cp_async16(base + soff,
                       A + (size_t)(bm + row) * K + k0 + col4);
            cp_async16(base + (uint32_t)(TSZ * 4) + soff,
                       Bt + (size_t)(bn + row) * K + k0 + col4);
        }
        cp_commit();
    };

    load_chunk(0);

    for (int c = 0; c < NCH; c++) {
        if (c + 1 < NCH) { load_chunk(c + 1); cp_wait<1>(); }
        else             { cp_wait<0>(); }
        __syncthreads();

        uint32_t base = smemBase + (uint32_t)((c & 1) * 2 * TSZ * 4);
        uint32_t aB = base + a_off;
        uint32_t bB = base + b_off;

        #pragma unroll
        for (int ks = 0; ks < 4; ks++) {
            uint32_t kOff = (uint32_t)(ks * 32);   // 8 floats
            uint32_t af[4][4], bf[4][2];
            #pragma unroll
            for (int mi = 0; mi < 4; mi++)
                ldsm_x4(af[mi][0], af[mi][1], af[mi][2], af[mi][3],
                        aB + kOff + (uint32_t)(mi * 16 * GSTR * 4));
            #pragma unroll
            for (int p = 0; p < 2; p++)
                ldsm_x4(bf[2*p][0], bf[2*p][1], bf[2*p+1][0], bf[2*p+1][1],
                        bB + kOff + (uint32_t)(p * 16 * GSTR * 4));
            #pragma unroll
            for (int mi = 0; mi < 4; mi++)
                #pragma unroll
                for (int ni = 0; ni < 4; ni++)
                    mma_16n8k8(acc[mi][ni], af[mi], bf[ni]);
        }
        __syncthreads();
    }

    #pragma unroll
    for (int mi = 0; mi < 4; mi++) {
        #pragma unroll
        for (int half = 0; half < 2; half++) {
            int row = bm + wm + mi * 16 + grp + half * 8;
            float* orow = Cout + (size_t)row * N + bn;
            const float* rrow = RESID ? (resid + (size_t)row * N + bn) : nullptr;
            #pragma unroll
            for (int ni = 0; ni < 4; ni++) {
                int col = wn + ni * 8 + tg * 2;
                float v0 = acc[mi][ni][half * 2 + 0];
                float v1 = acc[mi][ni][half * 2 + 1];
                if (BIAS) {
                    float2 bb = *(const float2*)(bias + bn + col);
                    v0 += bb.x; v1 += bb.y;
                }
                if (ACT == 1) { v0 = gelu_exact(v0); v1 = gelu_exact(v1); }
                if (RESID) {
                    float2 rr = *(const float2*)(rrow + col);
                    v0 += rr.x; v1 += rr.y;
                }
                if (ROUND_OUT) { v0 = cvtf_tf32(v0); v1 = cvtf_tf32(v1); }
                *(float2*)(orow + col) = make_float2(v0, v1);
            }
        }
    }
}

// ---------------------------------------------------------------------------
// Flash attention, mma.sync tf32 (qkv pre-rounded tf32) — unchanged from R5
// ---------------------------------------------------------------------------
#define ATT_STR 72
#define ATTN_SMEM_BYTES ((128 + 64 + 64 + 128) * ATT_STR * 4)

__global__ __launch_bounds__(128, 2) void attn_mma_kernel(
    const float* __restrict__ qkv, float* __restrict__ out)
{
    extern __shared__ float sm[];
    float* Qs = sm;
    float* Ks = Qs + 128 * ATT_STR;
    float* Vt = Ks + 64 * ATT_STR;
    float* Ps = Vt + 64 * ATT_STR;

    int qt = blockIdx.x, h = blockIdx.y, b = blockIdx.z;
    int t = threadIdx.x, lane = t & 31, w = t >> 5;
    int grp = lane >> 2, tg = lane & 3;

    const size_t tok0 = (size_t)b * T;

    #pragma unroll
    for (int it = 0; it < 16; it++) {
        int idx = t + it * 128;
        int row = idx >> 4;
        int c4  = (idx & 15) << 2;
        const float* p = qkv + (tok0 + qt * 128 + row) * C3 + h * D + c4;
        float4 v = *(const float4*)p;
        int base = c4 & ~7;
        int off  = (c4 & 4) ? 1 : 0;
        float* qr = Qs + row * ATT_STR + base + off;
        qr[0] = v.x * 0.125f;
        qr[2] = v.y * 0.125f;
        qr[4] = v.z * 0.125f;
        qr[6] = v.w * 0.125f;
    }

    float m[2][2], l[2][2];
    float oacc[2][8][4];
    #pragma unroll
    for (int mi = 0; mi < 2; mi++) {
        m[mi][0] = m[mi][1] = -1e30f;
        l[mi][0] = l[mi][1] = 0.f;
        #pragma unroll
        for (int nt = 0; nt < 8; nt++)
            #pragma unroll
            for (int r = 0; r < 4; r++) oacc[mi][nt][r] = 0.f;
    }

    int vkey  = t & 63;
    int vhalf = t >> 6;
    int pckey = (vkey & ~7) | (((vkey & 3) << 1) | ((vkey >> 2) & 1));
    int pc0 = (((tg * 2) & 3) << 1) | (((tg * 2) >> 2) & 1);
    int pc1 = (((tg * 2 + 1) & 3) << 1) | (((tg * 2 + 1) >> 2) & 1);

    float* PsW = Ps + w * 32 * ATT_STR;

    for (int kt = 0; kt < T; kt += 64) {
        __syncthreads();

        #pragma unroll
        for (int it = 0; it < 8; it++) {
            int idx = t + it * 128;
            int row = idx >> 4;
            int c4  = (idx & 15) << 2;
            const float* p = qkv + (tok0 + kt + row) * C3 + C + h * D + c4;
            float4 v = *(const float4*)p;
            int base = c4 & ~7;
            int off  = (c4 & 4) ? 1 : 0;
            float* kr = Ks + row * ATT_STR + base + off;
            kr[0] = v.x;
            kr[2] = v.y;
            kr[4] = v.z;
            kr[6] = v.w;
        }
        {
            const float* vp = qkv + (tok0 + kt + vkey) * C3 + 2 * C + h * D + vhalf * 32;
            #pragma unroll
            for (int j4 = 0; j4 < 8; j4++) {
                float4 v = *(const float4*)(vp + j4 * 4);
                int d = vhalf * 32 + j4 * 4;
                Vt[(d + 0) * ATT_STR + pckey] = v.x;
                Vt[(d + 1) * ATT_STR + pckey] = v.y;
                Vt[(d + 2) * ATT_STR + pckey] = v.z;
                Vt[(d + 3) * ATT_STR + pckey] = v.w;
            }
        }
        __syncthreads();

        float sacc[2][8][4];
        #pragma unroll
        for (int mi = 0; mi < 2; mi++)
            #pragma unroll
            for (int nt = 0; nt < 8; nt++)
                #pragma unroll
                for (int r = 0; r < 4; r++) sacc[mi][nt][r] = 0.f;

        #pragma unroll
        for (int ks = 0; ks < 8; ks++) {
            uint32_t a[2][4];
            #pragma unroll
            for (int mi = 0; mi < 2; mi++) {
                const float2 lo = *(const float2*)(Qs + (w * 32 + mi * 16 + grp)     * ATT_STR + ks * 8 + tg * 2);
                const float2 hi = *(const float2*)(Qs + (w * 32 + mi * 16 + grp + 8) * ATT_STR + ks * 8 + tg * 2);
                a[mi][0] = __float_as_uint(lo.x);
                a[mi][1] = __float_as_uint(hi.x);
                a[mi][2] = __float_as_uint(lo.y);
                a[mi][3] = __float_as_uint(hi.y);
            }
            #pragma unroll
            for (int nt = 0; nt < 8; nt++) {
                const float2 bb = *(const float2*)(Ks + (nt * 8 + grp) * ATT_STR + ks * 8 + tg * 2);
                uint32_t bfr[2] = { __float_as_uint(bb.x), __float_as_uint(bb.y) };
                mma_16n8k8(sacc[0][nt], a[0], bfr);
                mma_16n8k8(sacc[1][nt], a[1], bfr);
            }
        }

        #pragma unroll
        for (int mi = 0; mi < 2; mi++) {
            float r0 = -1e30f, r1 = -1e30f;
            #pragma unroll
            for (int nt = 0; nt < 8; nt++) {
                r0 = fmaxf(r0, fmaxf(sacc[mi][nt][0], sacc[mi][nt][1]));
                r1 = fmaxf(r1, fmaxf(sacc[mi][nt][2], sacc[mi][nt][3]));
            }
            r0 = fmaxf(r0, __shfl_xor_sync(0xffffffffu, r0, 1));
            r0 = fmaxf(r0, __shfl_xor_sync(0xffffffffu, r0, 2));
            r1 = fmaxf(r1, __shfl_xor_sync(0xffffffffu, r1, 1));
            r1 = fmaxf(r1, __shfl_xor_sync(0xffffffffu, r1, 2));
            float mn0 = fmaxf(m[mi][0], r0);
            float mn1 = fmaxf(m[mi][1], r1);
            float c0 = __expf(m[mi][0] - mn0);
            float c1 = __expf(m[mi][1] - mn1);
            m[mi][0] = mn0; m[mi][1] = mn1;
            l[mi][0] *= c0; l[mi][1] *= c1;
            #pragma unroll
            for (int nt = 0; nt < 8; nt++) {
                oacc[mi][nt][0] *= c0; oacc[mi][nt][1] *= c0;
                oacc[mi][nt][2] *= c1; oacc[mi][nt][3] *= c1;
            }
            float* plo = PsW + (mi * 16 + grp)     * ATT_STR;
            float* phi = PsW + (mi * 16 + grp + 8) * ATT_STR;
            #pragma unroll
            for (int nt = 0; nt < 8; nt++) {
                float p0 = __expf(sacc[mi][nt][0] - mn0);
                float p1 = __expf(sacc[mi][nt][1] - mn0);
                float p2 = __expf(sacc[mi][nt][2] - mn1);
                float p3 = __expf(sacc[mi][nt][3] - mn1);
                l[mi][0] += p0 + p1;
                l[mi][1] += p2 + p3;
                plo[nt * 8 + pc0] = cvtf_tf32(p0);
                plo[nt * 8 + pc1] = cvtf_tf32(p1);
                phi[nt * 8 + pc0] = cvtf_tf32(p2);
                phi[nt * 8 + pc1] = cvtf_tf32(p3);
            }
        }
        __syncwarp();

        #pragma unroll
        for (int ks = 0; ks < 8; ks++) {
            uint32_t a[2][4];
            #pragma unroll
            for (int mi = 0; mi < 2; mi++) {
                const float2 lo = *(const float2*)(PsW + (mi * 16 + grp)     * ATT_STR + ks * 8 + tg * 2);
                const float2 hi = *(const float2*)(PsW + (mi * 16 + grp + 8) * ATT_STR + ks * 8 + tg * 2);
                a[mi][0] = __float_as_uint(lo.x);
                a[mi][1] = __float_as_uint(hi.x);
                a[mi][2] = __float_as_uint(lo.y);
                a[mi][3] = __float_as_uint(hi.y);
            }
            #pragma unroll
            for (int nt = 0; nt < 8; nt++) {
                const float2 bb = *(const float2*)(Vt + (nt * 8 + grp) * ATT_STR + ks * 8 + tg * 2);
                uint32_t bfr[2] = { __float_as_uint(bb.x), __float_as_uint(bb.y) };
                mma_16n8k8(oacc[0][nt], a[0], bfr);
                mma_16n8k8(oacc[1][nt], a[1], bfr);
            }
        }
    }

    #pragma unroll
    for (int mi = 0; mi < 2; mi++) {
        float l0 = l[mi][0], l1 = l[mi][1];
        l0 += __shfl_xor_sync(0xffffffffu, l0, 1);
        l0 += __shfl_xor_sync(0xffffffffu, l0, 2);
        l1 += __shfl_xor_sync(0xffffffffu, l1, 1);
        l1 += __shfl_xor_sync(0xffffffffu, l1, 2);
        float i0 = 1.f / l0, i1 = 1.f / l1;
        int rlo = qt * 128 + w * 32 + mi * 16 + grp;
        float* olo = out + (tok0 + rlo) * C + h * D;
        float* ohi = out + (tok0 + rlo + 8) * C + h * D;
        #pragma unroll
        for (int nt = 0; nt < 8; nt++) {
            int col = nt * 8 + tg * 2;
            *(float2*)(olo + col) = make_float2(cvtf_tf32(oacc[mi][nt][0] * i0),
                                                cvtf_tf32(oacc[mi][nt][1] * i0));
            *(float2*)(ohi + col) = make_float2(cvtf_tf32(oacc[mi][nt][2] * i1),
                                                cvtf_tf32(oacc[mi][nt][3] * i1));
        }
    }
}

// ---------------------------------------------------------------------------
// Launch
// ---------------------------------------------------------------------------
extern "C" void kernel_launch(void* const* d_in, const int* in_sizes, int n_in,
                              void* d_out, int out_size)
{
    const float* x      = (const float*)d_in[0];
    const float* ln1_g  = (const float*)d_in[1];
    const float* ln1_b  = (const float*)d_in[2];
    const float* ln2_g  = (const float*)d_in[3];
    const float* ln2_b  = (const float*)d_in[4];
    const float* w_qkv  = (const float*)d_in[5];
    const float* w_proj = (const float*)d_in[6];
    const float* w1     = (const float*)d_in[7];
    const float* b1     = (const float*)d_in[8];
    const float* w2     = (const float*)d_in[9];
    const float* b2     = (const float*)d_in[10];
    float* out = (float*)d_out;

    float* ln   = nullptr;  cudaGetSymbolAddress((void**)&ln,   g_ln);
    float* qkv  = nullptr;  cudaGetSymbolAddress((void**)&qkv,  g_qkv);
    float* attn = nullptr;  cudaGetSymbolAddress((void**)&attn, g_attn);
    float* h1   = nullptr;  cudaGetSymbolAddress((void**)&h1,   g_h1);
    float* wt   = nullptr;  cudaGetSymbolAddress((void**)&wt,   g_wt);

    cudaFuncSetAttribute(gemm_mma<0, false, false, true >, cudaFuncAttributeMaxDynamicSharedMemorySize, GEMM_SMEM_BYTES);
    cudaFuncSetAttribute(gemm_mma<0, false, true,  false>, cudaFuncAttributeMaxDynamicSharedMemorySize, GEMM_SMEM_BYTES);
    cudaFuncSetAttribute(gemm_mma<1, true,  false, true >, cudaFuncAttributeMaxDynamicSharedMemorySize, GEMM_SMEM_BYTES);
    cudaFuncSetAttribute(gemm_mma<0, true,  true,  false>, cudaFuncAttributeMaxDynamicSharedMemorySize, GEMM_SMEM_BYTES);
    cudaFuncSetAttribute(attn_mma_kernel, cudaFuncAttributeMaxDynamicSharedMemorySize, ATTN_SMEM_BYTES);

    // 0) transpose + round weights: [K][N] -> [N][K] tf32
    {
        dim3 blk(32, 8);
        wtr_kernel<<<dim3(C3 / 32, C / 32), blk>>>(w_qkv,  wt + WT_QKV,  C,   C3);
        wtr_kernel<<<dim3(C  / 32, C / 32), blk>>>(w_proj, wt + WT_PROJ, C,   C);
        wtr_kernel<<<dim3(DFF / 32, C / 32), blk>>>(w1,    wt + WT_W1,   C,   DFF);
        wtr_kernel<<<dim3(C / 32, DFF / 32), blk>>>(w2,    wt + WT_W2,   DFF, C);
    }

    // 1) LN1(x) -> ln (tf32-rounded)
    ln_kernel<<<BT, 256>>>(x, ln1_g, ln1_b, ln);

    // 2) qkv = ln @ w_qkv
    gemm_mma<0, false, false, true><<<dim3(C3 / 128, BT / 128), 256, GEMM_SMEM_BYTES>>>(
        ln, wt + WT_QKV, nullptr, nullptr, qkv, BT, C3, C);

    // 3) attention
    attn_mma_kernel<<<dim3(T / 128, H, 4), 128, ATTN_SMEM_BYTES>>>(qkv, attn);

    // 4) out = x + attn @ w_proj
    gemm_mma<0, false, true, false><<<dim3(C / 128, BT / 128), 256, GEMM_SMEM_BYTES>>>(
        attn, wt + WT_PROJ, nullptr, x, out, BT, C, C);

    // 5) LN2(out) -> ln
    ln_kernel<<<BT, 256>>>(out, ln2_g, ln2_b, ln);

    // 6) h1 = gelu(ln @ w1 + b1)
    gemm_mma<1, true, false, true><<<dim3(DFF / 128, BT / 128), 256, GEMM_SMEM_BYTES>>>(
        ln, wt + WT_W1, b1, nullptr, h1, BT, DFF, C);

    // 7) out = out + h1 @ w2 + b2
    gemm_mma<0, true, true, false><<<dim3(C / 128, BT / 128), 256, GEMM_SMEM_BYTES>>>(
        h1, wt + WT_W2, b2, out, out, BT, C, DFF);
}

// round 8
// speedup vs baseline: 1.2253x; 1.0042x over previous
#include <cuda_runtime.h>
#include <math.h>
#include <stdint.h>

// ---------------------------------------------------------------------------
// TransformerBlock: mma.sync tf32 GEMMs (ldmatrix, 64x64 warp tile, B
// pre-transposed, 2-stage cp.async) + tf32 flash attention
// Shapes: B=4, T=2048 (BT=8192), C=1024, H=16, D=64, DFF=4096
// ---------------------------------------------------------------------------

#define BT   8192
#define C    1024
#define C3   3072
#define H    16
#define D    64
#define DFF  4096
#define T    2048
#define EPS  1e-5f

// Scratch (__device__ globals; no allocations allowed)
__device__ float g_ln[BT * C];
__device__ float g_qkv[BT * C3];
__device__ float g_attn[BT * C];
__device__ float g_h1[BT * DFF];
// tf32-rounded TRANSPOSED weights: [N][K] layout
#define WT_QKV  0
#define WT_PROJ (WT_QKV + C * C3)
#define WT_W1   (WT_PROJ + C * C)
#define WT_W2   (WT_W1 + C * DFF)
#define WT_TOT  (WT_W2 + DFF * C)
__device__ float g_wt[WT_TOT];

// ---------------------------------------------------------------------------
// Helpers
// ---------------------------------------------------------------------------
__device__ __forceinline__ uint32_t smem_u32(const void* p) {
    uint32_t a;
    asm("{ .reg .u64 t; cvta.to.shared.u64 t, %1; cvt.u32.u64 %0, t; }" : "=r"(a) : "l"(p));
    return a;
}
__device__ __forceinline__ void cp_async16(uint32_t dst, const void* src) {
    asm volatile("cp.async.ca.shared.global [%0], [%1], 16;" :: "r"(dst), "l"(src) : "memory");
}
__device__ __forceinline__ void cp_commit() {
    asm volatile("cp.async.commit_group;" ::: "memory");
}
template<int N>
__device__ __forceinline__ void cp_wait() {
    asm volatile("cp.async.wait_group %0;" :: "n"(N) : "memory");
}
__device__ __forceinline__ uint32_t cvt_tf32(float x) {
    uint32_t u;
    asm("cvt.rna.tf32.f32 %0, %1;" : "=r"(u) : "f"(x));
    return u;
}
__device__ __forceinline__ float cvtf_tf32(float x) {
    return __uint_as_float(cvt_tf32(x));
}
__device__ __forceinline__ void ldsm_x4(uint32_t& r0, uint32_t& r1, uint32_t& r2, uint32_t& r3,
                                        uint32_t addr) {
    asm volatile("ldmatrix.sync.aligned.m8n8.x4.shared.b16 {%0,%1,%2,%3}, [%4];"
                 : "=r"(r0), "=r"(r1), "=r"(r2), "=r"(r3) : "r"(addr));
}
__device__ __forceinline__ void mma_16n8k8(float* d, const uint32_t* a, const uint32_t* b) {
    asm volatile(
        "mma.sync.aligned.m16n8k8.row.col.f32.tf32.tf32.f32 "
        "{%0,%1,%2,%3}, {%4,%5,%6,%7}, {%8,%9}, {%0,%1,%2,%3};"
        : "+f"(d[0]), "+f"(d[1]), "+f"(d[2]), "+f"(d[3])
        : "r"(a[0]), "r"(a[1]), "r"(a[2]), "r"(a[3]), "r"(b[0]), "r"(b[1]));
}
__device__ __forceinline__ float gelu_exact(float v) {
    return 0.5f * v * (1.0f + erff(v * 0.70710678118654752f));
}

// ---------------------------------------------------------------------------
// Weight transpose + tf32 round: in [K][N] -> out [N][K]
// ---------------------------------------------------------------------------
__global__ __launch_bounds__(256) void wtr_kernel(
    const float* __restrict__ in, float* __restrict__ out, int K, int N)
{
    __shared__ float tile[32][33];
    int n0 = blockIdx.x * 32, k0 = blockIdx.y * 32;
    int tx = threadIdx.x, ty = threadIdx.y;
    #pragma unroll
    for (int i = ty; i < 32; i += 8)
        tile[i][tx] = in[(size_t)(k0 + i) * N + n0 + tx];
    __syncthreads();
    #pragma unroll
    for (int i = ty; i < 32; i += 8)
        out[(size_t)(n0 + i) * K + k0 + tx] = cvtf_tf32(tile[tx][i]);
}

// ---------------------------------------------------------------------------
// LayerNorm (output tf32-rounded; sole consumer is a GEMM)
// ---------------------------------------------------------------------------
__global__ __launch_bounds__(256) void ln_kernel(
    const float* __restrict__ x, const float* __restrict__ g,
    const float* __restrict__ beta, float* __restrict__ out)
{
    int row = blockIdx.x;
    int t = threadIdx.x;
    const float* xr = x + (size_t)row * C;
    float4 xv = *(const float4*)(xr + t * 4);
    float s  = xv.x + xv.y + xv.z + xv.w;
    float s2 = xv.x * xv.x + xv.y * xv.y + xv.z * xv.z + xv.w * xv.w;
    #pragma unroll
    for (int o = 16; o > 0; o >>= 1) {
        s  += __shfl_xor_sync(0xffffffffu, s,  o);
        s2 += __shfl_xor_sync(0xffffffffu, s2, o);
    }
    __shared__ float ss[8], ss2[8];
    int w = t >> 5, lane = t & 31;
    if (lane == 0) { ss[w] = s; ss2[w] = s2; }
    __syncthreads();
    if (w == 0) {
        s  = (lane < 8) ? ss[lane]  : 0.f;
        s2 = (lane < 8) ? ss2[lane] : 0.f;
        #pragma unroll
        for (int o = 4; o > 0; o >>= 1) {
            s  += __shfl_xor_sync(0xffffffffu, s,  o);
            s2 += __shfl_xor_sync(0xffffffffu, s2, o);
        }
        if (lane == 0) { ss[0] = s; ss2[0] = s2; }
    }
    __syncthreads();
    float mu  = ss[0] * (1.0f / C);
    float var = ss2[0] * (1.0f / C) - mu * mu;
    float inv = rsqrtf(var + EPS);
    float4 gv = *(const float4*)(g + t * 4);
    float4 bv = *(const float4*)(beta + t * 4);
    float4 ov;
    ov.x = cvtf_tf32((xv.x - mu) * inv * gv.x + bv.x);
    ov.y = cvtf_tf32((xv.y - mu) * inv * gv.y + bv.y);
    ov.z = cvtf_tf32((xv.z - mu) * inv * gv.z + bv.z);
    ov.w = cvtf_tf32((xv.w - mu) * inv * gv.w + bv.w);
    *(float4*)(out + (size_t)row * C + t * 4) = ov;
}

// ---------------------------------------------------------------------------
// tf32 mma.sync GEMM: D[M,N] = A[M,K] @ Bt[N,K]^T (+bias)(gelu)(+resid)
// CTA 128x128, 128 threads (4 warps, 2x2), warp tile 64x64,
// K-chunk 32, 2-stage cp.async, ldmatrix fragment loads.
// ---------------------------------------------------------------------------
#define GSTR 36
#define TSZ (128 * GSTR)
#define NSTAGE 2
#define GEMM_SMEM_BYTES (NSTAGE * 2 * TSZ * 4)

template<int ACT, bool BIAS, bool RESID, bool ROUND_OUT>
__global__ __launch_bounds__(128, 2) void gemm_mma(
    const float* __restrict__ A, const float* __restrict__ Bt,
    const float* __restrict__ bias, const float* __restrict__ resid,
    float* __restrict__ Cout, int M, int N, int K)
{
    extern __shared__ float smem[];
    int t    = threadIdx.x;
    int lane = t & 31;
    int w    = t >> 5;
    int grp  = lane >> 2;
    int tg   = lane & 3;
    int bm = blockIdx.y * 128;
    int bn = blockIdx.x * 128;
    int wm = (w >> 1) * 64;
    int wn = (w & 1) * 64;

    uint32_t smemBase = smem_u32(smem);

    int lrow = lane & 7;
    int lsel = lane >> 3;
    // A fragment source: row += (lsel&1)*8, k-col += (lsel>>1)*4
    uint32_t a_off = (uint32_t)(((wm + lrow + (lsel & 1) * 8) * GSTR + (lsel >> 1) * 4) * 4);
    // B fragment source: n += (lsel>>1)*8, k-col += (lsel&1)*4
    uint32_t b_off = (uint32_t)(((wn + lrow + (lsel >> 1) * 8) * GSTR + (lsel & 1) * 4) * 4)
                   + (uint32_t)(TSZ * 4);

    float acc[4][8][4];
    #pragma unroll
    for (int mi = 0; mi < 4; mi++)
        #pragma unroll
        for (int ni = 0; ni < 8; ni++)
            #pragma unroll
            for (int r = 0; r < 4; r++) acc[mi][ni][r] = 0.f;

    const int NCH = K >> 5;

    auto load_chunk = [&](int c) {
        int buf = c & 1;
        uint32_t base = smemBase + (uint32_t)(buf * 2 * TSZ * 4);
        int k0 = c << 5;
        #pragma unroll
        for (int it = 0; it < 8; it++) {
            int idx  = t + it * 128;
            int row  = idx >> 3;
            int col4 = (idx & 7) << 2;
            uint32_t soff = (uint32_t)((row * GSTR + col4) * 4);
            cp_async16(base + soff,
                       A + (size_t)(bm + row) * K + k0 + col4);
            cp_async16(base + (uint32_t)(TSZ * 4) + soff,
                       Bt + (size_t)(bn + row) * K + k0 + col4);
        }
        cp_commit();
    };

    load_chunk(0);

    for (int c = 0; c < NCH; c++) {
        if (c + 1 < NCH) { load_chunk(c + 1); cp_wait<1>(); }
        else             { cp_wait<0>(); }
        __syncthreads();

        uint32_t base = smemBase + (uint32_t)((c & 1) * 2 * TSZ * 4);
        uint32_t aB = base + a_off;
        uint32_t bB = base + b_off;

        #pragma unroll
        for (int ks = 0; ks < 4; ks++) {
            uint32_t kOff = (uint32_t)(ks * 32);   // 8 floats
            uint32_t af[4][4], bf[8][2];
            #pragma unroll
            for (int mi = 0; mi < 4; mi++)
                ldsm_x4(af[mi][0], af[mi][1], af[mi][2], af[mi][3],
                        aB + kOff + (uint32_t)(mi * 16 * GSTR * 4));
            #pragma unroll
            for (int p = 0; p < 4; p++)
                ldsm_x4(bf[2*p][0], bf[2*p][1], bf[2*p+1][0], bf[2*p+1][1],
                        bB + kOff + (uint32_t)(p * 16 * GSTR * 4));
            #pragma unroll
            for (int mi = 0; mi < 4; mi++)
                #pragma unroll
                for (int ni = 0; ni < 8; ni++)
                    mma_16n8k8(acc[mi][ni], af[mi], bf[ni]);
        }
        __syncthreads();
    }

    #pragma unroll
    for (int mi = 0; mi < 4; mi++) {
        #pragma unroll
        for (int half = 0; half < 2; half++) {
            int row = bm + wm + mi * 16 + grp + half * 8;
            float* orow = Cout + (size_t)row * N + bn;
            const float* rrow = RESID ? (resid + (size_t)row * N + bn) : nullptr;
            #pragma unroll
            for (int ni = 0; ni < 8; ni++) {
                int col = wn + ni * 8 + tg * 2;
                float v0 = acc[mi][ni][half * 2 + 0];
                float v1 = acc[mi][ni][half * 2 + 1];
                if (BIAS) {
                    float2 bb = *(const float2*)(bias + bn + col);
                    v0 += bb.x; v1 += bb.y;
                }
                if (ACT == 1) { v0 = gelu_exact(v0); v1 = gelu_exact(v1); }
                if (RESID) {
                    float2 rr = *(const float2*)(rrow + col);
                    v0 += rr.x; v1 += rr.y;
                }
                if (ROUND_OUT) { v0 = cvtf_tf32(v0); v1 = cvtf_tf32(v1); }
                *(float2*)(orow + col) = make_float2(v0, v1);
            }
        }
    }
}

// ---------------------------------------------------------------------------
// Flash attention, mma.sync tf32 (qkv pre-rounded tf32) — unchanged
// ---------------------------------------------------------------------------
#define ATT_STR 72
#define ATTN_SMEM_BYTES ((128 + 64 + 64 + 128) * ATT_STR * 4)

__global__ __launch_bounds__(128, 2) void attn_mma_kernel(
    const float* __restrict__ qkv, float* __restrict__ out)
{
    extern __shared__ float sm[];
    float* Qs = sm;
    float* Ks = Qs + 128 * ATT_STR;
    float* Vt = Ks + 64 * ATT_STR;
    float* Ps = Vt + 64 * ATT_STR;

    int qt = blockIdx.x, h = blockIdx.y, b = blockIdx.z;
    int t = threadIdx.x, lane = t & 31, w = t >> 5;
    int grp = lane >> 2, tg = lane & 3;

    const size_t tok0 = (size_t)b * T;

    #pragma unroll
    for (int it = 0; it < 16; it++) {
        int idx = t + it * 128;
        int row = idx >> 4;
        int c4  = (idx & 15) << 2;
        const float* p = qkv + (tok0 + qt * 128 + row) * C3 + h * D + c4;
        float4 v = *(const float4*)p;
        int base = c4 & ~7;
        int off  = (c4 & 4) ? 1 : 0;
        float* qr = Qs + row * ATT_STR + base + off;
        qr[0] = v.x * 0.125f;
        qr[2] = v.y * 0.125f;
        qr[4] = v.z * 0.125f;
        qr[6] = v.w * 0.125f;
    }

    float m[2][2], l[2][2];
    float oacc[2][8][4];
    #pragma unroll
    for (int mi = 0; mi < 2; mi++) {
        m[mi][0] = m[mi][1] = -1e30f;
        l[mi][0] = l[mi][1] = 0.f;
        #pragma unroll
        for (int nt = 0; nt < 8; nt++)
            #pragma unroll
            for (int r = 0; r < 4; r++) oacc[mi][nt][r] = 0.f;
    }

    int vkey  = t & 63;
    int vhalf = t >> 6;
    int pckey = (vkey & ~7) | (((vkey & 3) << 1) | ((vkey >> 2) & 1));
    int pc0 = (((tg * 2) & 3) << 1) | (((tg * 2) >> 2) & 1);
    int pc1 = (((tg * 2 + 1) & 3) << 1) | (((tg * 2 + 1) >> 2) & 1);

    float* PsW = Ps + w * 32 * ATT_STR;

    for (int kt = 0; kt < T; kt += 64) {
        __syncthreads();

        #pragma unroll
        for (int it = 0; it < 8; it++) {
            int idx = t + it * 128;
            int row = idx >> 4;
            int c4  = (idx & 15) << 2;
            const float* p = qkv + (tok0 + kt + row) * C3 + C + h * D + c4;
            float4 v = *(const float4*)p;
            int base = c4 & ~7;
            int off  = (c4 & 4) ? 1 : 0;
            float* kr = Ks + row * ATT_STR + base + off;
            kr[0] = v.x;
            kr[2] = v.y;
            kr[4] = v.z;
            kr[6] = v.w;
        }
        {
            const float* vp = qkv + (tok0 + kt + vkey) * C3 + 2 * C + h * D + vhalf * 32;
            #pragma unroll
            for (int j4 = 0; j4 < 8; j4++) {
                float4 v = *(const float4*)(vp + j4 * 4);
                int d = vhalf * 32 + j4 * 4;
                Vt[(d + 0) * ATT_STR + pckey] = v.x;
                Vt[(d + 1) * ATT_STR + pckey] = v.y;
                Vt[(d + 2) * ATT_STR + pckey] = v.z;
                Vt[(d + 3) * ATT_STR + pckey] = v.w;
            }
        }
        __syncthreads();

        float sacc[2][8][4];
        #pragma unroll
        for (int mi = 0; mi < 2; mi++)
            #pragma unroll
            for (int nt = 0; nt < 8; nt++)
                #pragma unroll
                for (int r = 0; r < 4; r++) sacc[mi][nt][r] = 0.f;

        #pragma unroll
        for (int ks = 0; ks < 8; ks++) {
            uint32_t a[2][4];
            #pragma unroll
            for (int mi = 0; mi < 2; mi++) {
                const float2 lo = *(const float2*)(Qs + (w * 32 + mi * 16 + grp)     * ATT_STR + ks * 8 + tg * 2);
                const float2 hi = *(const float2*)(Qs + (w * 32 + mi * 16 + grp + 8) * ATT_STR + ks * 8 + tg * 2);
                a[mi][0] = __float_as_uint(lo.x);
                a[mi][1] = __float_as_uint(hi.x);
                a[mi][2] = __float_as_uint(lo.y);
                a[mi][3] = __float_as_uint(hi.y);
            }
            #pragma unroll
            for (int nt = 0; nt < 8; nt++) {
                const float2 bb = *(const float2*)(Ks + (nt * 8 + grp) * ATT_STR + ks * 8 + tg * 2);
                uint32_t bfr[2] = { __float_as_uint(bb.x), __float_as_uint(bb.y) };
                mma_16n8k8(sacc[0][nt], a[0], bfr);
                mma_16n8k8(sacc[1][nt], a[1], bfr);
            }
        }

        #pragma unroll
        for (int mi = 0; mi < 2; mi++) {
            float r0 = -1e30f, r1 = -1e30f;
            #pragma unroll
            for (int nt = 0; nt < 8; nt++) {
                r0 = fmaxf(r0, fmaxf(sacc[mi][nt][0], sacc[mi][nt][1]));
                r1 = fmaxf(r1, fmaxf(sacc[mi][nt][2], sacc[mi][nt][3]));
            }
            r0 = fmaxf(r0, __shfl_xor_sync(0xffffffffu, r0, 1));
            r0 = fmaxf(r0, __shfl_xor_sync(0xffffffffu, r0, 2));
            r1 = fmaxf(r1, __shfl_xor_sync(0xffffffffu, r1, 1));
            r1 = fmaxf(r1, __shfl_xor_sync(0xffffffffu, r1, 2));
            float mn0 = fmaxf(m[mi][0], r0);
            float mn1 = fmaxf(m[mi][1], r1);
            float c0 = __expf(m[mi][0] - mn0);
            float c1 = __expf(m[mi][1] - mn1);
            m[mi][0] = mn0; m[mi][1] = mn1;
            l[mi][0] *= c0; l[mi][1] *= c1;
            #pragma unroll
            for (int nt = 0; nt < 8; nt++) {
                oacc[mi][nt][0] *= c0; oacc[mi][nt][1] *= c0;
                oacc[mi][nt][2] *= c1; oacc[mi][nt][3] *= c1;
            }
            float* plo = PsW + (mi * 16 + grp)     * ATT_STR;
            float* phi = PsW + (mi * 16 + grp + 8) * ATT_STR;
            #pragma unroll
            for (int nt = 0; nt < 8; nt++) {
                float p0 = __expf(sacc[mi][nt][0] - mn0);
                float p1 = __expf(sacc[mi][nt][1] - mn0);
                float p2 = __expf(sacc[mi][nt][2] - mn1);
                float p3 = __expf(sacc[mi][nt][3] - mn1);
                l[mi][0] += p0 + p1;
                l[mi][1] += p2 + p3;
                plo[nt * 8 + pc0] = cvtf_tf32(p0);
                plo[nt * 8 + pc1] = cvtf_tf32(p1);
                phi[nt * 8 + pc0] = cvtf_tf32(p2);
                phi[nt * 8 + pc1] = cvtf_tf32(p3);
            }
        }
        __syncwarp();

        #pragma unroll
        for (int ks = 0; ks < 8; ks++) {
            uint32_t a[2][4];
            #pragma unroll
            for (int mi = 0; mi < 2; mi++) {
                const float2 lo = *(const float2*)(PsW + (mi * 16 + grp)     * ATT_STR + ks * 8 + tg * 2);
                const float2 hi = *(const float2*)(PsW + (mi * 16 + grp + 8) * ATT_STR + ks * 8 + tg * 2);
                a[mi][0] = __float_as_uint(lo.x);
                a[mi][1] = __float_as_uint(hi.x);
                a[mi][2] = __float_as_uint(lo.y);
                a[mi][3] = __float_as_uint(hi.y);
            }
            #pragma unroll
            for (int nt = 0; nt < 8; nt++) {
                const float2 bb = *(const float2*)(Vt + (nt * 8 + grp) * ATT_STR + ks * 8 + tg * 2);
                uint32_t bfr[2] = { __float_as_uint(bb.x), __float_as_uint(bb.y) };
                mma_16n8k8(oacc[0][nt], a[0], bfr);
                mma_16n8k8(oacc[1][nt], a[1], bfr);
            }
        }
    }

    #pragma unroll
    for (int mi = 0; mi < 2; mi++) {
        float l0 = l[mi][0], l1 = l[mi][1];
        l0 += __shfl_xor_sync(0xffffffffu, l0, 1);
        l0 += __shfl_xor_sync(0xffffffffu, l0, 2);
        l1 += __shfl_xor_sync(0xffffffffu, l1, 1);
        l1 += __shfl_xor_sync(0xffffffffu, l1, 2);
        float i0 = 1.f / l0, i1 = 1.f / l1;
        int rlo = qt * 128 + w * 32 + mi * 16 + grp;
        float* olo = out + (tok0 + rlo) * C + h * D;
        float* ohi = out + (tok0 + rlo + 8) * C + h * D;
        #pragma unroll
        for (int nt = 0; nt < 8; nt++) {
            int col = nt * 8 + tg * 2;
            *(float2*)(olo + col) = make_float2(cvtf_tf32(oacc[mi][nt][0] * i0),
                                                cvtf_tf32(oacc[mi][nt][1] * i0));
            *(float2*)(ohi + col) = make_float2(cvtf_tf32(oacc[mi][nt][2] * i1),
                                                cvtf_tf32(oacc[mi][nt][3] * i1));
        }
    }
}

// ---------------------------------------------------------------------------
// Launch
// ---------------------------------------------------------------------------
extern "C" void kernel_launch(void* const* d_in, const int* in_sizes, int n_in,
                              void* d_out, int out_size)
{
    const float* x      = (const float*)d_in[0];
    const float* ln1_g  = (const float*)d_in[1];
    const float* ln1_b  = (const float*)d_in[2];
    const float* ln2_g  = (const float*)d_in[3];
    const float* ln2_b  = (const float*)d_in[4];
    const float* w_qkv  = (const float*)d_in[5];
    const float* w_proj = (const float*)d_in[6];
    const float* w1     = (const float*)d_in[7];
    const float* b1     = (const float*)d_in[8];
    const float* w2     = (const float*)d_in[9];
    const float* b2     = (const float*)d_in[10];
    float* out = (float*)d_out;

    float* ln   = nullptr;  cudaGetSymbolAddress((void**)&ln,   g_ln);
    float* qkv  = nullptr;  cudaGetSymbolAddress((void**)&qkv,  g_qkv);
    float* attn = nullptr;  cudaGetSymbolAddress((void**)&attn, g_attn);
    float* h1   = nullptr;  cudaGetSymbolAddress((void**)&h1,   g_h1);
    float* wt   = nullptr;  cudaGetSymbolAddress((void**)&wt,   g_wt);

    cudaFuncSetAttribute(gemm_mma<0, false, false, true >, cudaFuncAttributeMaxDynamicSharedMemorySize, GEMM_SMEM_BYTES);
    cudaFuncSetAttribute(gemm_mma<0, false, true,  false>, cudaFuncAttributeMaxDynamicSharedMemorySize, GEMM_SMEM_BYTES);
    cudaFuncSetAttribute(gemm_mma<1, true,  false, true >, cudaFuncAttributeMaxDynamicSharedMemorySize, GEMM_SMEM_BYTES);
    cudaFuncSetAttribute(gemm_mma<0, true,  true,  false>, cudaFuncAttributeMaxDynamicSharedMemorySize, GEMM_SMEM_BYTES);
    cudaFuncSetAttribute(attn_mma_kernel, cudaFuncAttributeMaxDynamicSharedMemorySize, ATTN_SMEM_BYTES);

    // 0) transpose + round weights: [K][N] -> [N][K] tf32
    {
        dim3 blk(32, 8);
        wtr_kernel<<<dim3(C3 / 32, C / 32), blk>>>(w_qkv,  wt + WT_QKV,  C,   C3);
        wtr_kernel<<<dim3(C  / 32, C / 32), blk>>>(w_proj, wt + WT_PROJ, C,   C);
        wtr_kernel<<<dim3(DFF / 32, C / 32), blk>>>(w1,    wt + WT_W1,   C,   DFF);
        wtr_kernel<<<dim3(C / 32, DFF / 32), blk>>>(w2,    wt + WT_W2,   DFF, C);
    }

    // 1) LN1(x) -> ln (tf32-rounded)
    ln_kernel<<<BT, 256>>>(x, ln1_g, ln1_b, ln);

    // 2) qkv = ln @ w_qkv
    gemm_mma<0, false, false, true><<<dim3(C3 / 128, BT / 128), 128, GEMM_SMEM_BYTES>>>(
        ln, wt + WT_QKV, nullptr, nullptr, qkv, BT, C3, C);

    // 3) attention
    attn_mma_kernel<<<dim3(T / 128, H, 4), 128, ATTN_SMEM_BYTES>>>(qkv, attn);

    // 4) out = x + attn @ w_proj
    gemm_mma<0, false, true, false><<<dim3(C / 128, BT / 128), 128, GEMM_SMEM_BYTES>>>(
        attn, wt + WT_PROJ, nullptr, x, out, BT, C, C);

    // 5) LN2(out) -> ln
    ln_kernel<<<BT, 256>>>(out, ln2_g, ln2_b, ln);

    // 6) h1 = gelu(ln @ w1 + b1)
    gemm_mma<1, true, false, true><<<dim3(DFF / 128, BT / 128), 128, GEMM_SMEM_BYTES>>>(
        ln, wt + WT_W1, b1, nullptr, h1, BT, DFF, C);

    // 7) out = out + h1 @ w2 + b2
    gemm_mma<0, true, true, false><<<dim3(C / 128, BT / 128), 128, GEMM_SMEM_BYTES>>>(
        h1, wt + WT_W2, b2, out, out, BT, C, DFF);
}

// round 9
// speedup vs baseline: 2.4898x; 2.0319x over previous
#include <cuda_runtime.h>
#include <cuda_fp16.h>
#include <math.h>
#include <stdint.h>

// ---------------------------------------------------------------------------
// TransformerBlock: fp16 m16n8k16 mma.sync GEMMs + fp16 flash attention.
// fp32 residual stream; fp16 (10-bit mantissa == tf32) for all GEMM operands.
// Shapes: B=4, T=2048 (BT=8192), C=1024, H=16, D=64, DFF=4096
// ---------------------------------------------------------------------------

#define BT   8192
#define C    1024
#define C3   3072
#define H    16
#define D    64
#define DFF  4096
#define T    2048
#define EPS  1e-5f

// Scratch (__device__ globals; no allocations allowed)
__device__ __half g_ln[BT * C];
__device__ __half g_qkv[BT * C3];
__device__ __half g_attn[BT * C];
__device__ __half g_h1[BT * DFF];
// fp16 TRANSPOSED weights: [N][K]
#define WT_QKV  0
#define WT_PROJ (WT_QKV + C * C3)
#define WT_W1   (WT_PROJ + C * C)
#define WT_W2   (WT_W1 + C * DFF)
#define WT_TOT  (WT_W2 + DFF * C)
__device__ __half g_wt[WT_TOT];

// ---------------------------------------------------------------------------
// Helpers
// ---------------------------------------------------------------------------
__device__ __forceinline__ uint32_t smem_u32(const void* p) {
    uint32_t a;
    asm("{ .reg .u64 t; cvta.to.shared.u64 t, %1; cvt.u32.u64 %0, t; }" : "=r"(a) : "l"(p));
    return a;
}
__device__ __forceinline__ void cp_async16(uint32_t dst, const void* src) {
    asm volatile("cp.async.ca.shared.global [%0], [%1], 16;" :: "r"(dst), "l"(src) : "memory");
}
__device__ __forceinline__ void cp_commit() {
    asm volatile("cp.async.commit_group;" ::: "memory");
}
template<int N>
__device__ __forceinline__ void cp_wait() {
    asm volatile("cp.async.wait_group %0;" :: "n"(N) : "memory");
}
__device__ __forceinline__ void ldsm_x4(uint32_t& r0, uint32_t& r1, uint32_t& r2, uint32_t& r3,
                                        uint32_t addr) {
    asm volatile("ldmatrix.sync.aligned.m8n8.x4.shared.b16 {%0,%1,%2,%3}, [%4];"
                 : "=r"(r0), "=r"(r1), "=r"(r2), "=r"(r3) : "r"(addr));
}
__device__ __forceinline__ void mma_16n8k16(float* d, const uint32_t* a, const uint32_t* b) {
    asm volatile(
        "mma.sync.aligned.m16n8k16.row.col.f32.f16.f16.f32 "
        "{%0,%1,%2,%3}, {%4,%5,%6,%7}, {%8,%9}, {%0,%1,%2,%3};"
        : "+f"(d[0]), "+f"(d[1]), "+f"(d[2]), "+f"(d[3])
        : "r"(a[0]), "r"(a[1]), "r"(a[2]), "r"(a[3]), "r"(b[0]), "r"(b[1]));
}
__device__ __forceinline__ float gelu_exact(float v) {
    return 0.5f * v * (1.0f + erff(v * 0.70710678118654752f));
}

// ---------------------------------------------------------------------------
// Weight transpose + fp16 convert: in fp32 [K][N] -> out fp16 [N][K]
// ---------------------------------------------------------------------------
__global__ __launch_bounds__(256) void wtr_kernel(
    const float* __restrict__ in, __half* __restrict__ out, int K, int N)
{
    __shared__ float tile[32][33];
    int n0 = blockIdx.x * 32, k0 = blockIdx.y * 32;
    int tx = threadIdx.x, ty = threadIdx.y;
    #pragma unroll
    for (int i = ty; i < 32; i += 8)
        tile[i][tx] = in[(size_t)(k0 + i) * N + n0 + tx];
    __syncthreads();
    #pragma unroll
    for (int i = ty; i < 32; i += 8)
        out[(size_t)(n0 + i) * K + k0 + tx] = __float2half(tile[tx][i]);
}

// ---------------------------------------------------------------------------
// LayerNorm (fp32 in, fp16 out; sole consumer is a GEMM)
// ---------------------------------------------------------------------------
__global__ __launch_bounds__(256) void ln_kernel(
    const float* __restrict__ x, const float* __restrict__ g,
    const float* __restrict__ beta, __half* __restrict__ out)
{
    int row = blockIdx.x;
    int t = threadIdx.x;
    const float* xr = x + (size_t)row * C;
    float4 xv = *(const float4*)(xr + t * 4);
    float s  = xv.x + xv.y + xv.z + xv.w;
    float s2 = xv.x * xv.x + xv.y * xv.y + xv.z * xv.z + xv.w * xv.w;
    #pragma unroll
    for (int o = 16; o > 0; o >>= 1) {
        s  += __shfl_xor_sync(0xffffffffu, s,  o);
        s2 += __shfl_xor_sync(0xffffffffu, s2, o);
    }
    __shared__ float ss[8], ss2[8];
    int w = t >> 5, lane = t & 31;
    if (lane == 0) { ss[w] = s; ss2[w] = s2; }
    __syncthreads();
    if (w == 0) {
        s  = (lane < 8) ? ss[lane]  : 0.f;
        s2 = (lane < 8) ? ss2[lane] : 0.f;
        #pragma unroll
        for (int o = 4; o > 0; o >>= 1) {
            s  += __shfl_xor_sync(0xffffffffu, s,  o);
            s2 += __shfl_xor_sync(0xffffffffu, s2, o);
        }
        if (lane == 0) { ss[0] = s; ss2[0] = s2; }
    }
    __syncthreads();
    float mu  = ss[0] * (1.0f / C);
    float var = ss2[0] * (1.0f / C) - mu * mu;
    float inv = rsqrtf(var + EPS);
    float4 gv = *(const float4*)(g + t * 4);
    float4 bv = *(const float4*)(beta + t * 4);
    __half2* o = (__half2*)(out + (size_t)row * C + t * 4);
    o[0] = __floats2half2_rn((xv.x - mu) * inv * gv.x + bv.x,
                             (xv.y - mu) * inv * gv.y + bv.y);
    o[1] = __floats2half2_rn((xv.z - mu) * inv * gv.z + bv.z,
                             (xv.w - mu) * inv * gv.w + bv.w);
}

// ---------------------------------------------------------------------------
// fp16 mma.sync GEMM: D[M,N] = A[M,K] @ Bt[N,K]^T (+bias)(gelu)(+resid)
// CTA 128x128, 128 threads (4 warps 2x2), warp tile 64x64, K-chunk 32,
// 2-stage cp.async, ldmatrix b16.
// Smem rows: 32 halves data, stride 40 halves (80B) -> conflict-free ldmatrix.
// ---------------------------------------------------------------------------
#define HSTR 40
#define TILE_BYTES (128 * HSTR * 2)      // 10240
#define STAGE_BYTES (2 * TILE_BYTES)     // 20480
#define NSTAGE 2
#define GEMM_SMEM_BYTES (NSTAGE * STAGE_BYTES)

template<int ACT, bool BIAS, bool RESID, bool OUT_HALF>
__global__ __launch_bounds__(128, 2) void gemm_fp16(
    const __half* __restrict__ A, const __half* __restrict__ Bt,
    const float* __restrict__ bias, const float* __restrict__ resid,
    void* __restrict__ CoutV, int M, int N, int K)
{
    extern __shared__ char smem[];
    int t    = threadIdx.x;
    int lane = t & 31;
    int w    = t >> 5;
    int grp  = lane >> 2;
    int tg   = lane & 3;
    int bm = blockIdx.y * 128;
    int bn = blockIdx.x * 128;
    int wm = (w >> 1) * 64;
    int wn = (w & 1) * 64;

    uint32_t smemBase = smem_u32(smem);

    int lrow = lane & 7;
    int lsel = lane >> 3;
    // A fragment tiles: row += (lsel&1)*8, k += (lsel>>1)*8 halves
    uint32_t a_off = (uint32_t)(((wm + lrow + (lsel & 1) * 8) * HSTR + (lsel >> 1) * 8) * 2);
    // B fragment tiles: n += (lsel>>1)*8, k += (lsel&1)*8 halves
    uint32_t b_off = (uint32_t)(((wn + lrow + (lsel >> 1) * 8) * HSTR + (lsel & 1) * 8) * 2)
                   + (uint32_t)TILE_BYTES;

    float acc[4][8][4];
    #pragma unroll
    for (int mi = 0; mi < 4; mi++)
        #pragma unroll
        for (int ni = 0; ni < 8; ni++)
            #pragma unroll
            for (int r = 0; r < 4; r++) acc[mi][ni][r] = 0.f;

    const int NCH = K >> 5;

    auto load_chunk = [&](int c) {
        int buf = c & 1;
        uint32_t base = smemBase + (uint32_t)(buf * STAGE_BYTES);
        int k0 = c << 5;
        #pragma unroll
        for (int it = 0; it < 4; it++) {
            int idx   = t + it * 128;
            int row   = idx >> 2;
            int col16 = idx & 3;
            uint32_t soff = (uint32_t)(row * (HSTR * 2) + col16 * 16);
            cp_async16(base + soff,
                       A + (size_t)(bm + row) * K + k0 + col16 * 8);
            cp_async16(base + (uint32_t)TILE_BYTES + soff,
                       Bt + (size_t)(bn + row) * K + k0 + col16 * 8);
        }
        cp_commit();
    };

    load_chunk(0);

    for (int c = 0; c < NCH; c++) {
        if (c + 1 < NCH) { load_chunk(c + 1); cp_wait<1>(); }
        else             { cp_wait<0>(); }
        __syncthreads();

        uint32_t base = smemBase + (uint32_t)((c & 1) * STAGE_BYTES);
        uint32_t aB = base + a_off;
        uint32_t bB = base + b_off;

        #pragma unroll
        for (int ks = 0; ks < 2; ks++) {
            uint32_t kOff = (uint32_t)(ks * 32);   // 16 halves
            uint32_t af[4][4], bf[8][2];
            #pragma unroll
            for (int mi = 0; mi < 4; mi++)
                ldsm_x4(af[mi][0], af[mi][1], af[mi][2], af[mi][3],
                        aB + kOff + (uint32_t)(mi * 16 * HSTR * 2));
            #pragma unroll
            for (int p = 0; p < 4; p++)
                ldsm_x4(bf[2*p][0], bf[2*p][1], bf[2*p+1][0], bf[2*p+1][1],
                        bB + kOff + (uint32_t)(p * 16 * HSTR * 2));
            #pragma unroll
            for (int mi = 0; mi < 4; mi++)
                #pragma unroll
                for (int ni = 0; ni < 8; ni++)
                    mma_16n8k16(acc[mi][ni], af[mi], bf[ni]);
        }
        __syncthreads();
    }

    #pragma unroll
    for (int mi = 0; mi < 4; mi++) {
        #pragma unroll
        for (int half = 0; half < 2; half++) {
            int row = bm + wm + mi * 16 + grp + half * 8;
            const float* rrow = RESID ? (resid + (size_t)row * N + bn) : nullptr;
            #pragma unroll
            for (int ni = 0; ni < 8; ni++) {
                int col = wn + ni * 8 + tg * 2;
                float v0 = acc[mi][ni][half * 2 + 0];
                float v1 = acc[mi][ni][half * 2 + 1];
                if (BIAS) {
                    float2 bb = *(const float2*)(bias + bn + col);
                    v0 += bb.x; v1 += bb.y;
                }
                if (ACT == 1) { v0 = gelu_exact(v0); v1 = gelu_exact(v1); }
                if (RESID) {
                    float2 rr = *(const float2*)(rrow + col);
                    v0 += rr.x; v1 += rr.y;
                }
                if (OUT_HALF) {
                    __half* orow = (__half*)CoutV + (size_t)row * N + bn;
                    *(__half2*)(orow + col) = __floats2half2_rn(v0, v1);
                } else {
                    float* orow = (float*)CoutV + (size_t)row * N + bn;
                    *(float2*)(orow + col) = make_float2(v0, v1);
                }
            }
        }
    }
}

// ---------------------------------------------------------------------------
// Flash attention, fp16 m16n8k16.
// CTA: 128 q-rows, 4 warps x 32 rows; key chunks of 64.
// Smem (halves, row stride 72 = 144B, conflict-free ldmatrix):
//   Qs[128][72], Ks[64][72], Vt[64][72] ([d][key]), Ps[4*32][72]
// ---------------------------------------------------------------------------
#define ASTR 72
#define ATTN_SMEM_BYTES ((128 + 64 + 64 + 128) * ASTR * 2)

__global__ __launch_bounds__(128, 2) void attn_mma_kernel(
    const __half* __restrict__ qkv, __half* __restrict__ out)
{
    extern __shared__ char sm[];
    __half* Qs = (__half*)sm;
    __half* Ks = Qs + 128 * ASTR;
    __half* Vt = Ks + 64 * ASTR;
    __half* Ps = Vt + 64 * ASTR;

    int qt = blockIdx.x, h = blockIdx.y, b = blockIdx.z;
    int t = threadIdx.x, lane = t & 31, w = t >> 5;
    int grp = lane >> 2, tg = lane & 3;
    int lrow = lane & 7, lsel = lane >> 3;

    const size_t tok0 = (size_t)b * T;

    // ---- stage Q (scaled by 0.125, exact in fp16) ----
    {
        __half2 sc = __float2half2_rn(0.125f);
        #pragma unroll
        for (int it = 0; it < 8; it++) {
            int idx   = t + it * 128;
            int row   = idx >> 3;
            int col16 = idx & 7;
            const __half* p = qkv + (tok0 + qt * 128 + row) * C3 + h * D + col16 * 8;
            uint4 v = *(const uint4*)p;
            __half2* hv = (__half2*)&v;
            hv[0] = __hmul2(hv[0], sc);
            hv[1] = __hmul2(hv[1], sc);
            hv[2] = __hmul2(hv[2], sc);
            hv[3] = __hmul2(hv[3], sc);
            *(uint4*)(Qs + row * ASTR + col16 * 8) = v;
        }
    }

    float m[2][2], l[2][2];
    float oacc[2][8][4];
    #pragma unroll
    for (int mi = 0; mi < 2; mi++) {
        m[mi][0] = m[mi][1] = -1e30f;
        l[mi][0] = l[mi][1] = 0.f;
        #pragma unroll
        for (int nt = 0; nt < 8; nt++)
            #pragma unroll
            for (int r = 0; r < 4; r++) oacc[mi][nt][r] = 0.f;
    }

    int vkey  = t & 63;
    int vhalf = t >> 6;

    // fragment base offsets (bytes)
    uint32_t QsB = smem_u32(Qs);
    uint32_t KsB = smem_u32(Ks);
    uint32_t VtB = smem_u32(Vt);
    uint32_t PsB = smem_u32(Ps);
    uint32_t aq_off = (uint32_t)(((w * 32 + lrow + (lsel & 1) * 8) * ASTR + (lsel >> 1) * 8) * 2);
    uint32_t ap_off = (uint32_t)(((w * 32 + lrow + (lsel & 1) * 8) * ASTR + (lsel >> 1) * 8) * 2);
    uint32_t bn_off = (uint32_t)(((lrow + (lsel >> 1) * 8) * ASTR + (lsel & 1) * 8) * 2);

    __half* PsW = Ps + w * 32 * ASTR;

    for (int kt = 0; kt < T; kt += 64) {
        __syncthreads();

        // ---- stage K chunk: 64 rows x 64 halves ----
        #pragma unroll
        for (int it = 0; it < 4; it++) {
            int idx   = t + it * 128;
            int row   = idx >> 3;
            int col16 = idx & 7;
            const __half* p = qkv + (tok0 + kt + row) * C3 + C + h * D + col16 * 8;
            *(uint4*)(Ks + row * ASTR + col16 * 8) = *(const uint4*)p;
        }
        // ---- stage V transposed: Vt[d][key] ----
        {
            const __half* vp = qkv + (tok0 + kt + vkey) * C3 + 2 * C + h * D + vhalf * 32;
            #pragma unroll
            for (int j = 0; j < 4; j++) {
                uint4 v = *(const uint4*)(vp + j * 8);
                const __half* hp = (const __half*)&v;
                int d0 = vhalf * 32 + j * 8;
                #pragma unroll
                for (int i = 0; i < 8; i++)
                    Vt[(d0 + i) * ASTR + vkey] = hp[i];
            }
        }
        __syncthreads();

        // ---- S = Q @ K^T  (k = D = 64 -> 4 ksteps) ----
        float sacc[2][8][4];
        #pragma unroll
        for (int mi = 0; mi < 2; mi++)
            #pragma unroll
            for (int nt = 0; nt < 8; nt++)
                #pragma unroll
                for (int r = 0; r < 4; r++) sacc[mi][nt][r] = 0.f;

        #pragma unroll
        for (int ks = 0; ks < 4; ks++) {
            uint32_t kOff = (uint32_t)(ks * 32);
            uint32_t af[2][4], bf[8][2];
            #pragma unroll
            for (int mi = 0; mi < 2; mi++)
                ldsm_x4(af[mi][0], af[mi][1], af[mi][2], af[mi][3],
                        QsB + aq_off + kOff + (uint32_t)(mi * 16 * ASTR * 2));
            #pragma unroll
            for (int p = 0; p < 4; p++)
                ldsm_x4(bf[2*p][0], bf[2*p][1], bf[2*p+1][0], bf[2*p+1][1],
                        KsB + bn_off + kOff + (uint32_t)(p * 16 * ASTR * 2));
            #pragma unroll
            for (int mi = 0; mi < 2; mi++)
                #pragma unroll
                for (int nt = 0; nt < 8; nt++)
                    mma_16n8k16(sacc[mi][nt], af[mi], bf[nt]);
        }

        // ---- online softmax + P store (fp16) ----
        #pragma unroll
        for (int mi = 0; mi < 2; mi++) {
            float r0 = -1e30f, r1 = -1e30f;
            #pragma unroll
            for (int nt = 0; nt < 8; nt++) {
                r0 = fmaxf(r0, fmaxf(sacc[mi][nt][0], sacc[mi][nt][1]));
                r1 = fmaxf(r1, fmaxf(sacc[mi][nt][2], sacc[mi][nt][3]));
            }
            r0 = fmaxf(r0, __shfl_xor_sync(0xffffffffu, r0, 1));
            r0 = fmaxf(r0, __shfl_xor_sync(0xffffffffu, r0, 2));
            r1 = fmaxf(r1, __shfl_xor_sync(0xffffffffu, r1, 1));
            r1 = fmaxf(r1, __shfl_xor_sync(0xffffffffu, r1, 2));
            float mn0 = fmaxf(m[mi][0], r0);
            float mn1 = fmaxf(m[mi][1], r1);
            float c0 = __expf(m[mi][0] - mn0);
            float c1 = __expf(m[mi][1] - mn1);
            m[mi][0] = mn0; m[mi][1] = mn1;
            l[mi][0] *= c0; l[mi][1] *= c1;
            #pragma unroll
            for (int nt = 0; nt < 8; nt++) {
                oacc[mi][nt][0] *= c0; oacc[mi][nt][1] *= c0;
                oacc[mi][nt][2] *= c1; oacc[mi][nt][3] *= c1;
            }
            __half* plo = PsW + (mi * 16 + grp)     * ASTR;
            __half* phi = PsW + (mi * 16 + grp + 8) * ASTR;
            #pragma unroll
            for (int nt = 0; nt < 8; nt++) {
                float p0 = __expf(sacc[mi][nt][0] - mn0);
                float p1 = __expf(sacc[mi][nt][1] - mn0);
                float p2 = __expf(sacc[mi][nt][2] - mn1);
                float p3 = __expf(sacc[mi][nt][3] - mn1);
                l[mi][0] += p0 + p1;
                l[mi][1] += p2 + p3;
                int col = nt * 8 + tg * 2;
                *(__half2*)(plo + col) = __floats2half2_rn(p0, p1);
                *(__half2*)(phi + col) = __floats2half2_rn(p2, p3);
            }
        }
        __syncwarp();

        // ---- O += P @ V  (k = 64 keys -> 4 ksteps) ----
        #pragma unroll
        for (int ks = 0; ks < 4; ks++) {
            uint32_t kOff = (uint32_t)(ks * 32);
            uint32_t af[2][4], bf[8][2];
            #pragma unroll
            for (int mi = 0; mi < 2; mi++)
                ldsm_x4(af[mi][0], af[mi][1], af[mi][2], af[mi][3],
                        PsB + ap_off + kOff + (uint32_t)(mi * 16 * ASTR * 2));
            #pragma unroll
            for (int p = 0; p < 4; p++)
                ldsm_x4(bf[2*p][0], bf[2*p][1], bf[2*p+1][0], bf[2*p+1][1],
                        VtB + bn_off + kOff + (uint32_t)(p * 16 * ASTR * 2));
            #pragma unroll
            for (int mi = 0; mi < 2; mi++)
                #pragma unroll
                for (int nt = 0; nt < 8; nt++)
                    mma_16n8k16(oacc[mi][nt], af[mi], bf[nt]);
        }
    }

    // ---- finalize ----
    #pragma unroll
    for (int mi = 0; mi < 2; mi++) {
        float l0 = l[mi][0], l1 = l[mi][1];
        l0 += __shfl_xor_sync(0xffffffffu, l0, 1);
        l0 += __shfl_xor_sync(0xffffffffu, l0, 2);
        l1 += __shfl_xor_sync(0xffffffffu, l1, 1);
        l1 += __shfl_xor_sync(0xffffffffu, l1, 2);
        float i0 = 1.f / l0, i1 = 1.f / l1;
        int rlo = qt * 128 + w * 32 + mi * 16 + grp;
        __half* olo = out + (tok0 + rlo) * C + h * D;
        __half* ohi = out + (tok0 + rlo + 8) * C + h * D;
        #pragma unroll
        for (int nt = 0; nt < 8; nt++) {
            int col = nt * 8 + tg * 2;
            *(__half2*)(olo + col) = __floats2half2_rn(oacc[mi][nt][0] * i0,
                                                       oacc[mi][nt][1] * i0);
            *(__half2*)(ohi + col) = __floats2half2_rn(oacc[mi][nt][2] * i1,
                                                       oacc[mi][nt][3] * i1);
        }
    }
}

// ---------------------------------------------------------------------------
// Launch
// ---------------------------------------------------------------------------
extern "C" void kernel_launch(void* const* d_in, const int* in_sizes, int n_in,
                              void* d_out, int out_size)
{
    const float* x      = (const float*)d_in[0];
    const float* ln1_g  = (const float*)d_in[1];
    const float* ln1_b  = (const float*)d_in[2];
    const float* ln2_g  = (const float*)d_in[3];
    const float* ln2_b  = (const float*)d_in[4];
    const float* w_qkv  = (const float*)d_in[5];
    const float* w_proj = (const float*)d_in[6];
    const float* w1     = (const float*)d_in[7];
    const float* b1     = (const float*)d_in[8];
    const float* w2     = (const float*)d_in[9];
    const float* b2     = (const float*)d_in[10];
    float* out = (float*)d_out;

    __half* ln   = nullptr;  cudaGetSymbolAddress((void**)&ln,   g_ln);
    __half* qkv  = nullptr;  cudaGetSymbolAddress((void**)&qkv,  g_qkv);
    __half* attn = nullptr;  cudaGetSymbolAddress((void**)&attn, g_attn);
    __half* h1   = nullptr;  cudaGetSymbolAddress((void**)&h1,   g_h1);
    __half* wt   = nullptr;  cudaGetSymbolAddress((void**)&wt,   g_wt);

    cudaFuncSetAttribute(gemm_fp16<0, false, false, true >, cudaFuncAttributeMaxDynamicSharedMemorySize, GEMM_SMEM_BYTES);
    cudaFuncSetAttribute(gemm_fp16<0, false, true,  false>, cudaFuncAttributeMaxDynamicSharedMemorySize, GEMM_SMEM_BYTES);
    cudaFuncSetAttribute(gemm_fp16<1, true,  false, true >, cudaFuncAttributeMaxDynamicSharedMemorySize, GEMM_SMEM_BYTES);
    cudaFuncSetAttribute(gemm_fp16<0, true,  true,  false>, cudaFuncAttributeMaxDynamicSharedMemorySize, GEMM_SMEM_BYTES);
    cudaFuncSetAttribute(attn_mma_kernel, cudaFuncAttributeMaxDynamicSharedMemorySize, ATTN_SMEM_BYTES);

    // 0) transpose + convert weights: fp32 [K][N] -> fp16 [N][K]
    {
        dim3 blk(32, 8);
        wtr_kernel<<<dim3(C3 / 32, C / 32), blk>>>(w_qkv,  wt + WT_QKV,  C,   C3);
        wtr_kernel<<<dim3(C  / 32, C / 32), blk>>>(w_proj, wt + WT_PROJ, C,   C);
        wtr_kernel<<<dim3(DFF / 32, C / 32), blk>>>(w1,    wt + WT_W1,   C,   DFF);
        wtr_kernel<<<dim3(C / 32, DFF / 32), blk>>>(w2,    wt + WT_W2,   DFF, C);
    }

    // 1) LN1(x) -> ln (fp16)
    ln_kernel<<<BT, 256>>>(x, ln1_g, ln1_b, ln);

    // 2) qkv = ln @ w_qkv (fp16 out)
    gemm_fp16<0, false, false, true><<<dim3(C3 / 128, BT / 128), 128, GEMM_SMEM_BYTES>>>(
        ln, wt + WT_QKV, nullptr, nullptr, qkv, BT, C3, C);

    // 3) attention (fp16 in/out)
    attn_mma_kernel<<<dim3(T / 128, H, 4), 128, ATTN_SMEM_BYTES>>>(qkv, attn);

    // 4) out = x + attn @ w_proj (fp32 out)
    gemm_fp16<0, false, true, false><<<dim3(C / 128, BT / 128), 128, GEMM_SMEM_BYTES>>>(
        attn, wt + WT_PROJ, nullptr, x, out, BT, C, C);

    // 5) LN2(out) -> ln (fp16)
    ln_kernel<<<BT, 256>>>(out, ln2_g, ln2_b, ln);

    // 6) h1 = gelu(ln @ w1 + b1) (fp16 out)
    gemm_fp16<1, true, false, true><<<dim3(DFF / 128, BT / 128), 128, GEMM_SMEM_BYTES>>>(
        ln, wt + WT_W1, b1, nullptr, h1, BT, DFF, C);

    // 7) out = out + h1 @ w2 + b2 (fp32 out)
    gemm_fp16<0, true, true, false><<<dim3(C / 128, BT / 128), 128, GEMM_SMEM_BYTES>>>(
        h1, wt + WT_W2, b2, out, out, BT, C, DFF);
}

// round 10
// speedup vs baseline: 3.0248x; 1.2149x over previous
#include <cuda_runtime.h>
#include <cuda_fp16.h>
#include <math.h>
#include <stdint.h>

// ---------------------------------------------------------------------------
// TransformerBlock: fp16 m16n8k16 mma.sync GEMMs + fp16 flash attention
// (P-in-register, ldmatrix.trans V, cp.async pipelines everywhere).
// Shapes: B=4, T=2048 (BT=8192), C=1024, H=16, D=64, DFF=4096
// ---------------------------------------------------------------------------

#define BT   8192
#define C    1024
#define C3   3072
#define H    16
#define D    64
#define DFF  4096
#define T    2048
#define EPS  1e-5f

// Scratch (__device__ globals; no allocations allowed)
__device__ __half g_ln[BT * C];
__device__ __half g_qkv[BT * C3];
__device__ __half g_attn[BT * C];
__device__ __half g_h1[BT * DFF];
// fp16 TRANSPOSED weights: [N][K]
#define WT_QKV  0
#define WT_PROJ (WT_QKV + C * C3)
#define WT_W1   (WT_PROJ + C * C)
#define WT_W2   (WT_W1 + C * DFF)
#define WT_TOT  (WT_W2 + DFF * C)
__device__ __half g_wt[WT_TOT];

// ---------------------------------------------------------------------------
// Helpers
// ---------------------------------------------------------------------------
__device__ __forceinline__ uint32_t smem_u32(const void* p) {
    uint32_t a;
    asm("{ .reg .u64 t; cvta.to.shared.u64 t, %1; cvt.u32.u64 %0, t; }" : "=r"(a) : "l"(p));
    return a;
}
__device__ __forceinline__ void cp_async16(uint32_t dst, const void* src) {
    asm volatile("cp.async.ca.shared.global [%0], [%1], 16;" :: "r"(dst), "l"(src) : "memory");
}
__device__ __forceinline__ void cp_commit() {
    asm volatile("cp.async.commit_group;" ::: "memory");
}
template<int N>
__device__ __forceinline__ void cp_wait() {
    asm volatile("cp.async.wait_group %0;" :: "n"(N) : "memory");
}
__device__ __forceinline__ void ldsm_x4(uint32_t& r0, uint32_t& r1, uint32_t& r2, uint32_t& r3,
                                        uint32_t addr) {
    asm volatile("ldmatrix.sync.aligned.m8n8.x4.shared.b16 {%0,%1,%2,%3}, [%4];"
                 : "=r"(r0), "=r"(r1), "=r"(r2), "=r"(r3) : "r"(addr));
}
__device__ __forceinline__ void ldsm_x4_trans(uint32_t& r0, uint32_t& r1, uint32_t& r2, uint32_t& r3,
                                              uint32_t addr) {
    asm volatile("ldmatrix.sync.aligned.m8n8.x4.trans.shared.b16 {%0,%1,%2,%3}, [%4];"
                 : "=r"(r0), "=r"(r1), "=r"(r2), "=r"(r3) : "r"(addr));
}
__device__ __forceinline__ void mma_16n8k16(float* d, const uint32_t* a, const uint32_t* b) {
    asm volatile(
        "mma.sync.aligned.m16n8k16.row.col.f32.f16.f16.f32 "
        "{%0,%1,%2,%3}, {%4,%5,%6,%7}, {%8,%9}, {%0,%1,%2,%3};"
        : "+f"(d[0]), "+f"(d[1]), "+f"(d[2]), "+f"(d[3])
        : "r"(a[0]), "r"(a[1]), "r"(a[2]), "r"(a[3]), "r"(b[0]), "r"(b[1]));
}
__device__ __forceinline__ uint32_t pack_h2(float a, float b) {
    __half2 h = __floats2half2_rn(a, b);
    return *(uint32_t*)&h;
}
__device__ __forceinline__ float gelu_exact(float v) {
    return 0.5f * v * (1.0f + erff(v * 0.70710678118654752f));
}

// ---------------------------------------------------------------------------
// Weight transpose + fp16 convert: in fp32 [K][N] -> out fp16 [N][K]
// 64x64 tile, vectorized both phases.
// ---------------------------------------------------------------------------
__global__ __launch_bounds__(256) void wtr_kernel(
    const float* __restrict__ in, __half* __restrict__ out, int K, int N)
{
    __shared__ float tile[64][65];
    int n0 = blockIdx.x * 64, k0 = blockIdx.y * 64;
    int t = threadIdx.x;
    #pragma unroll
    for (int it = 0; it < 4; it++) {
        int idx = t + it * 256;
        int kr = idx >> 4;
        int nc = (idx & 15) << 2;
        float4 v = *(const float4*)(in + (size_t)(k0 + kr) * N + n0 + nc);
        tile[kr][nc] = v.x; tile[kr][nc + 1] = v.y;
        tile[kr][nc + 2] = v.z; tile[kr][nc + 3] = v.w;
    }
    __syncthreads();
    #pragma unroll
    for (int it = 0; it < 2; it++) {
        int idx = t + it * 256;
        int nr = idx >> 3;
        int kc = (idx & 7) << 3;
        __half h[8];
        #pragma unroll
        for (int i = 0; i < 8; i++) h[i] = __float2half(tile[kc + i][nr]);
        *(uint4*)(out + (size_t)(n0 + nr) * K + k0 + kc) = *(uint4*)h;
    }
}

// ---------------------------------------------------------------------------
// LayerNorm (fp32 in, fp16 out)
// ---------------------------------------------------------------------------
__global__ __launch_bounds__(256) void ln_kernel(
    const float* __restrict__ x, const float* __restrict__ g,
    const float* __restrict__ beta, __half* __restrict__ out)
{
    int row = blockIdx.x;
    int t = threadIdx.x;
    const float* xr = x + (size_t)row * C;
    float4 xv = *(const float4*)(xr + t * 4);
    float s  = xv.x + xv.y + xv.z + xv.w;
    float s2 = xv.x * xv.x + xv.y * xv.y + xv.z * xv.z + xv.w * xv.w;
    #pragma unroll
    for (int o = 16; o > 0; o >>= 1) {
        s  += __shfl_xor_sync(0xffffffffu, s,  o);
        s2 += __shfl_xor_sync(0xffffffffu, s2, o);
    }
    __shared__ float ss[8], ss2[8];
    int w = t >> 5, lane = t & 31;
    if (lane == 0) { ss[w] = s; ss2[w] = s2; }
    __syncthreads();
    if (w == 0) {
        s  = (lane < 8) ? ss[lane]  : 0.f;
        s2 = (lane < 8) ? ss2[lane] : 0.f;
        #pragma unroll
        for (int o = 4; o > 0; o >>= 1) {
            s  += __shfl_xor_sync(0xffffffffu, s,  o);
            s2 += __shfl_xor_sync(0xffffffffu, s2, o);
        }
        if (lane == 0) { ss[0] = s; ss2[0] = s2; }
    }
    __syncthreads();
    float mu  = ss[0] * (1.0f / C);
    float var = ss2[0] * (1.0f / C) - mu * mu;
    float inv = rsqrtf(var + EPS);
    float4 gv = *(const float4*)(g + t * 4);
    float4 bv = *(const float4*)(beta + t * 4);
    __half2* o = (__half2*)(out + (size_t)row * C + t * 4);
    o[0] = __floats2half2_rn((xv.x - mu) * inv * gv.x + bv.x,
                             (xv.y - mu) * inv * gv.y + bv.y);
    o[1] = __floats2half2_rn((xv.z - mu) * inv * gv.z + bv.z,
                             (xv.w - mu) * inv * gv.w + bv.w);
}

// ---------------------------------------------------------------------------
// fp16 mma.sync GEMM: D[M,N] = A[M,K] @ Bt[N,K]^T (+bias)(gelu)(+resid)
// CTA 128x128, 128 threads (4 warps 2x2), warp tile 64x64, K-chunk 32,
// THREE-stage cp.async with ONE barrier per chunk, ldmatrix b16.
// ---------------------------------------------------------------------------
#define HSTR 40
#define TILE_BYTES (128 * HSTR * 2)      // 10240
#define STAGE_BYTES (2 * TILE_BYTES)     // 20480
#define NSTAGE 3
#define GEMM_SMEM_BYTES (NSTAGE * STAGE_BYTES)

template<int ACT, bool BIAS, bool RESID, bool OUT_HALF>
__global__ __launch_bounds__(128, 2) void gemm_fp16(
    const __half* __restrict__ A, const __half* __restrict__ Bt,
    const float* __restrict__ bias, const float* __restrict__ resid,
    void* __restrict__ CoutV, int M, int N, int K)
{
    extern __shared__ char smem[];
    int t    = threadIdx.x;
    int lane = t & 31;
    int w    = t >> 5;
    int grp  = lane >> 2;
    int tg   = lane & 3;
    int bm = blockIdx.y * 128;
    int bn = blockIdx.x * 128;
    int wm = (w >> 1) * 64;
    int wn = (w & 1) * 64;

    uint32_t smemBase = smem_u32(smem);

    int lrow = lane & 7;
    int lsel = lane >> 3;
    uint32_t a_off = (uint32_t)(((wm + lrow + (lsel & 1) * 8) * HSTR + (lsel >> 1) * 8) * 2);
    uint32_t b_off = (uint32_t)(((wn + lrow + (lsel >> 1) * 8) * HSTR + (lsel & 1) * 8) * 2)
                   + (uint32_t)TILE_BYTES;

    float acc[4][8][4];
    #pragma unroll
    for (int mi = 0; mi < 4; mi++)
        #pragma unroll
        for (int ni = 0; ni < 8; ni++)
            #pragma unroll
            for (int r = 0; r < 4; r++) acc[mi][ni][r] = 0.f;

    const int NCH = K >> 5;

    auto load_chunk = [&](int c) {
        int buf = c % NSTAGE;
        uint32_t base = smemBase + (uint32_t)(buf * STAGE_BYTES);
        int k0 = c << 5;
        #pragma unroll
        for (int it = 0; it < 4; it++) {
            int idx   = t + it * 128;
            int row   = idx >> 2;
            int col16 = idx & 3;
            uint32_t soff = (uint32_t)(row * (HSTR * 2) + col16 * 16);
            cp_async16(base + soff,
                       A + (size_t)(bm + row) * K + k0 + col16 * 8);
            cp_async16(base + (uint32_t)TILE_BYTES + soff,
                       Bt + (size_t)(bn + row) * K + k0 + col16 * 8);
        }
        cp_commit();
    };

    load_chunk(0);
    load_chunk(1);

    for (int c = 0; c < NCH; c++) {
        if (c + 1 < NCH) cp_wait<1>(); else cp_wait<0>();
        __syncthreads();
        if (c + 2 < NCH) load_chunk(c + 2);

        uint32_t base = smemBase + (uint32_t)((c % NSTAGE) * STAGE_BYTES);
        uint32_t aB = base + a_off;
        uint32_t bB = base + b_off;

        #pragma unroll
        for (int ks = 0; ks < 2; ks++) {
            uint32_t kOff = (uint32_t)(ks * 32);
            uint32_t af[4][4], bf[8][2];
            #pragma unroll
            for (int mi = 0; mi < 4; mi++)
                ldsm_x4(af[mi][0], af[mi][1], af[mi][2], af[mi][3],
                        aB + kOff + (uint32_t)(mi * 16 * HSTR * 2));
            #pragma unroll
            for (int p = 0; p < 4; p++)
                ldsm_x4(bf[2*p][0], bf[2*p][1], bf[2*p+1][0], bf[2*p+1][1],
                        bB + kOff + (uint32_t)(p * 16 * HSTR * 2));
            #pragma unroll
            for (int mi = 0; mi < 4; mi++)
                #pragma unroll
                for (int ni = 0; ni < 8; ni++)
                    mma_16n8k16(acc[mi][ni], af[mi], bf[ni]);
        }
    }

    #pragma unroll
    for (int mi = 0; mi < 4; mi++) {
        #pragma unroll
        for (int half = 0; half < 2; half++) {
            int row = bm + wm + mi * 16 + grp + half * 8;
            const float* rrow = RESID ? (resid + (size_t)row * N + bn) : nullptr;
            #pragma unroll
            for (int ni = 0; ni < 8; ni++) {
                int col = wn + ni * 8 + tg * 2;
                float v0 = acc[mi][ni][half * 2 + 0];
                float v1 = acc[mi][ni][half * 2 + 1];
                if (BIAS) {
                    float2 bb = *(const float2*)(bias + bn + col);
                    v0 += bb.x; v1 += bb.y;
                }
                if (ACT == 1) { v0 = gelu_exact(v0); v1 = gelu_exact(v1); }
                if (RESID) {
                    float2 rr = *(const float2*)(rrow + col);
                    v0 += rr.x; v1 += rr.y;
                }
                if (OUT_HALF) {
                    __half* orow = (__half*)CoutV + (size_t)row * N + bn;
                    *(__half2*)(orow + col) = __floats2half2_rn(v0, v1);
                } else {
                    float* orow = (float*)CoutV + (size_t)row * N + bn;
                    *(float2*)(orow + col) = make_float2(v0, v1);
                }
            }
        }
    }
}

// ---------------------------------------------------------------------------
// Flash attention, fp16 m16n8k16.
// CTA: 128 q-rows, 4 warps x 32 rows; key chunks of 64.
// P stays in registers (S-acc fragment == PV A-fragment).
// V loaded row-major, B-fragments via ldmatrix.trans.
// K/V staged with 3-stage cp.async, one barrier per chunk.
// Smem: Qs[128][72] + 3 x (Ks[64][72] | Vs[64][72])  (halves)
// ---------------------------------------------------------------------------
#define ASTR 72
#define Q_BYTES   (128 * ASTR * 2)       // 18432
#define KV_BYTES  (64 * ASTR * 2)        // 9216
#define AST_BYTES (2 * KV_BYTES)         // 18432 per stage
#define ATTN_SMEM_BYTES (Q_BYTES + 3 * AST_BYTES)

__global__ __launch_bounds__(128, 2) void attn_mma_kernel(
    const __half* __restrict__ qkv, __half* __restrict__ out)
{
    extern __shared__ char sm[];
    uint32_t smBase = smem_u32(sm);
    __half* Qs = (__half*)sm;

    int qt = blockIdx.x, h = blockIdx.y, b = blockIdx.z;
    int t = threadIdx.x, lane = t & 31, w = t >> 5;
    int grp = lane >> 2, tg = lane & 3;
    int lrow = lane & 7, lsel = lane >> 3;

    const size_t tok0 = (size_t)b * T;
    const int NCHK = T / 64;

    // ---- stage Q (scaled by 0.125, exact in fp16) ----
    {
        __half2 sc = __float2half2_rn(0.125f);
        #pragma unroll
        for (int it = 0; it < 8; it++) {
            int idx   = t + it * 128;
            int row   = idx >> 3;
            int col16 = idx & 7;
            const __half* p = qkv + (tok0 + qt * 128 + row) * C3 + h * D + col16 * 8;
            uint4 v = *(const uint4*)p;
            __half2* hv = (__half2*)&v;
            hv[0] = __hmul2(hv[0], sc);
            hv[1] = __hmul2(hv[1], sc);
            hv[2] = __hmul2(hv[2], sc);
            hv[3] = __hmul2(hv[3], sc);
            *(uint4*)(Qs + row * ASTR + col16 * 8) = v;
        }
    }

    // K/V staging via cp.async
    auto stage_kv = [&](int c) {
        uint32_t base = smBase + (uint32_t)Q_BYTES + (uint32_t)((c % 3) * AST_BYTES);
        int kt = c * 64;
        #pragma unroll
        for (int it = 0; it < 4; it++) {
            int idx   = t + it * 128;
            int row   = idx >> 3;
            int col16 = idx & 7;
            uint32_t soff = (uint32_t)(row * (ASTR * 2) + col16 * 16);
            const __half* kp = qkv + (tok0 + kt + row) * C3 + C + h * D + col16 * 8;
            cp_async16(base + soff, kp);
            cp_async16(base + (uint32_t)KV_BYTES + soff, kp + C);
        }
        cp_commit();
    };

    stage_kv(0);
    stage_kv(1);
    __syncthreads();   // Q visible (STS) before ldsm

    // ---- hoist Q fragments to registers ----
    uint32_t aq_off = (uint32_t)(((w * 32 + lrow + (lsel & 1) * 8) * ASTR + (lsel >> 1) * 8) * 2);
    uint32_t qf[2][4][4];
    #pragma unroll
    for (int mi = 0; mi < 2; mi++)
        #pragma unroll
        for (int ks = 0; ks < 4; ks++)
            ldsm_x4(qf[mi][ks][0], qf[mi][ks][1], qf[mi][ks][2], qf[mi][ks][3],
                    smBase + aq_off + (uint32_t)(mi * 16 * ASTR * 2) + (uint32_t)(ks * 32));

    float m[2][2], l[2][2];
    float oacc[2][8][4];
    #pragma unroll
    for (int mi = 0; mi < 2; mi++) {
        m[mi][0] = m[mi][1] = -1e30f;
        l[mi][0] = l[mi][1] = 0.f;
        #pragma unroll
        for (int nt = 0; nt < 8; nt++)
            #pragma unroll
            for (int r = 0; r < 4; r++) oacc[mi][nt][r] = 0.f;
    }

    // fragment offsets
    uint32_t bn_off  = (uint32_t)(((lrow + (lsel >> 1) * 8) * ASTR + (lsel & 1) * 8) * 2);
    uint32_t vtr_off = (uint32_t)(((lrow + (lsel & 1) * 8) * ASTR + (lsel >> 1) * 8) * 2);

    for (int c = 0; c < NCHK; c++) {
        if (c + 1 < NCHK) cp_wait<1>(); else cp_wait<0>();
        __syncthreads();
        if (c + 2 < NCHK) stage_kv(c + 2);

        uint32_t stBase = smBase + (uint32_t)Q_BYTES + (uint32_t)((c % 3) * AST_BYTES);
        uint32_t KsB = stBase;
        uint32_t VsB = stBase + (uint32_t)KV_BYTES;

        // ---- S = Q @ K^T ----
        float sacc[2][8][4];
        #pragma unroll
        for (int mi = 0; mi < 2; mi++)
            #pragma unroll
            for (int nt = 0; nt < 8; nt++)
                #pragma unroll
                for (int r = 0; r < 4; r++) sacc[mi][nt][r] = 0.f;

        #pragma unroll
        for (int ks = 0; ks < 4; ks++) {
            uint32_t bf[8][2];
            #pragma unroll
            for (int p = 0; p < 4; p++)
                ldsm_x4(bf[2*p][0], bf[2*p][1], bf[2*p+1][0], bf[2*p+1][1],
                        KsB + bn_off + (uint32_t)(p * 16 * ASTR * 2) + (uint32_t)(ks * 32));
            #pragma unroll
            for (int mi = 0; mi < 2; mi++)
                #pragma unroll
                for (int nt = 0; nt < 8; nt++)
                    mma_16n8k16(sacc[mi][nt], qf[mi][ks], bf[nt]);
        }

        // ---- online softmax: exp into sacc (P in registers) ----
        #pragma unroll
        for (int mi = 0; mi < 2; mi++) {
            float r0 = -1e30f, r1 = -1e30f;
            #pragma unroll
            for (int nt = 0; nt < 8; nt++) {
                r0 = fmaxf(r0, fmaxf(sacc[mi][nt][0], sacc[mi][nt][1]));
                r1 = fmaxf(r1, fmaxf(sacc[mi][nt][2], sacc[mi][nt][3]));
            }
            r0 = fmaxf(r0, __shfl_xor_sync(0xffffffffu, r0, 1));
            r0 = fmaxf(r0, __shfl_xor_sync(0xffffffffu, r0, 2));
            r1 = fmaxf(r1, __shfl_xor_sync(0xffffffffu, r1, 1));
            r1 = fmaxf(r1, __shfl_xor_sync(0xffffffffu, r1, 2));
            float mn0 = fmaxf(m[mi][0], r0);
            float mn1 = fmaxf(m[mi][1], r1);
            float c0 = __expf(m[mi][0] - mn0);
            float c1 = __expf(m[mi][1] - mn1);
            m[mi][0] = mn0; m[mi][1] = mn1;
            l[mi][0] *= c0; l[mi][1] *= c1;
            #pragma unroll
            for (int nt = 0; nt < 8; nt++) {
                oacc[mi][nt][0] *= c0; oacc[mi][nt][1] *= c0;
                oacc[mi][nt][2] *= c1; oacc[mi][nt][3] *= c1;
            }
            #pragma unroll
            for (int nt = 0; nt < 8; nt++) {
                float p0 = __expf(sacc[mi][nt][0] - mn0);
                float p1 = __expf(sacc[mi][nt][1] - mn0);
                float p2 = __expf(sacc[mi][nt][2] - mn1);
                float p3 = __expf(sacc[mi][nt][3] - mn1);
                l[mi][0] += p0 + p1;
                l[mi][1] += p2 + p3;
                sacc[mi][nt][0] = p0; sacc[mi][nt][1] = p1;
                sacc[mi][nt][2] = p2; sacc[mi][nt][3] = p3;
            }
        }

        // ---- O += P @ V  (A from registers, B via ldmatrix.trans) ----
        #pragma unroll
        for (int ks = 0; ks < 4; ks++) {
            uint32_t bf[8][2];
            #pragma unroll
            for (int p = 0; p < 4; p++)
                ldsm_x4_trans(bf[2*p][0], bf[2*p][1], bf[2*p+1][0], bf[2*p+1][1],
                              VsB + vtr_off + (uint32_t)(ks * 16 * ASTR * 2) + (uint32_t)(p * 32));
            uint32_t af[2][4];
            #pragma unroll
            for (int mi = 0; mi < 2; mi++) {
                af[mi][0] = pack_h2(sacc[mi][2*ks][0],   sacc[mi][2*ks][1]);
                af[mi][1] = pack_h2(sacc[mi][2*ks][2],   sacc[mi][2*ks][3]);
                af[mi][2] = pack_h2(sacc[mi][2*ks+1][0], sacc[mi][2*ks+1][1]);
                af[mi][3] = pack_h2(sacc[mi][2*ks+1][2], sacc[mi][2*ks+1][3]);
            }
            #pragma unroll
            for (int mi = 0; mi < 2; mi++)
                #pragma unroll
                for (int nt = 0; nt < 8; nt++)
                    mma_16n8k16(oacc[mi][nt], af[mi], bf[nt]);
        }
    }

    // ---- finalize ----
    #pragma unroll
    for (int mi = 0; mi < 2; mi++) {
        float l0 = l[mi][0], l1 = l[mi][1];
        l0 += __shfl_xor_sync(0xffffffffu, l0, 1);
        l0 += __shfl_xor_sync(0xffffffffu, l0, 2);
        l1 += __shfl_xor_sync(0xffffffffu, l1, 1);
        l1 += __shfl_xor_sync(0xffffffffu, l1, 2);
        float i0 = 1.f / l0, i1 = 1.f / l1;
        int rlo = qt * 128 + w * 32 + mi * 16 + grp;
        __half* olo = out + (tok0 + rlo) * C + h * D;
        __half* ohi = out + (tok0 + rlo + 8) * C + h * D;
        #pragma unroll
        for (int nt = 0; nt < 8; nt++) {
            int col = nt * 8 + tg * 2;
            *(__half2*)(olo + col) = __floats2half2_rn(oacc[mi][nt][0] * i0,
                                                       oacc[mi][nt][1] * i0);
            *(__half2*)(ohi + col) = __floats2half2_rn(oacc[mi][nt][2] * i1,
                                                       oacc[mi][nt][3] * i1);
        }
    }
}

// ---------------------------------------------------------------------------
// Launch
// ---------------------------------------------------------------------------
extern "C" void kernel_launch(void* const* d_in, const int* in_sizes, int n_in,
                              void* d_out, int out_size)
{
    const float* x      = (const float*)d_in[0];
    const float* ln1_g  = (const float*)d_in[1];
    const float* ln1_b  = (const float*)d_in[2];
    const float* ln2_g  = (const float*)d_in[3];
    const float* ln2_b  = (const float*)d_in[4];
    const float* w_qkv  = (const float*)d_in[5];
    const float* w_proj = (const float*)d_in[6];
    const float* w1     = (const float*)d_in[7];
    const float* b1     = (const float*)d_in[8];
    const float* w2     = (const float*)d_in[9];
    const float* b2     = (const float*)d_in[10];
    float* out = (float*)d_out;

    __half* ln   = nullptr;  cudaGetSymbolAddress((void**)&ln,   g_ln);
    __half* qkv  = nullptr;  cudaGetSymbolAddress((void**)&qkv,  g_qkv);
    __half* attn = nullptr;  cudaGetSymbolAddress((void**)&attn, g_attn);
    __half* h1   = nullptr;  cudaGetSymbolAddress((void**)&h1,   g_h1);
    __half* wt   = nullptr;  cudaGetSymbolAddress((void**)&wt,   g_wt);

    cudaFuncSetAttribute(gemm_fp16<0, false, false, true >, cudaFuncAttributeMaxDynamicSharedMemorySize, GEMM_SMEM_BYTES);
    cudaFuncSetAttribute(gemm_fp16<0, false, true,  false>, cudaFuncAttributeMaxDynamicSharedMemorySize, GEMM_SMEM_BYTES);
    cudaFuncSetAttribute(gemm_fp16<1, true,  false, true >, cudaFuncAttributeMaxDynamicSharedMemorySize, GEMM_SMEM_BYTES);
    cudaFuncSetAttribute(gemm_fp16<0, true,  true,  false>, cudaFuncAttributeMaxDynamicSharedMemorySize, GEMM_SMEM_BYTES);
    cudaFuncSetAttribute(attn_mma_kernel, cudaFuncAttributeMaxDynamicSharedMemorySize, ATTN_SMEM_BYTES);

    // 0) transpose + convert weights: fp32 [K][N] -> fp16 [N][K]
    wtr_kernel<<<dim3(C3 / 64, C / 64), 256>>>(w_qkv,  wt + WT_QKV,  C,   C3);
    wtr_kernel<<<dim3(C  / 64, C / 64), 256>>>(w_proj, wt + WT_PROJ, C,   C);
    wtr_kernel<<<dim3(DFF / 64, C / 64), 256>>>(w1,    wt + WT_W1,   C,   DFF);
    wtr_kernel<<<dim3(C / 64, DFF / 64), 256>>>(w2,    wt + WT_W2,   DFF, C);

    // 1) LN1(x) -> ln (fp16)
    ln_kernel<<<BT, 256>>>(x, ln1_g, ln1_b, ln);

    // 2) qkv = ln @ w_qkv (fp16 out)
    gemm_fp16<0, false, false, true><<<dim3(C3 / 128, BT / 128), 128, GEMM_SMEM_BYTES>>>(
        ln, wt + WT_QKV, nullptr, nullptr, qkv, BT, C3, C);

    // 3) attention (fp16 in/out)
    attn_mma_kernel<<<dim3(T / 128, H, 4), 128, ATTN_SMEM_BYTES>>>(qkv, attn);

    // 4) out = x + attn @ w_proj (fp32 out)
    gemm_fp16<0, false, true, false><<<dim3(C / 128, BT / 128), 128, GEMM_SMEM_BYTES>>>(
        attn, wt + WT_PROJ, nullptr, x, out, BT, C, C);

    // 5) LN2(out) -> ln (fp16)
    ln_kernel<<<BT, 256>>>(out, ln2_g, ln2_b, ln);

    // 6) h1 = gelu(ln @ w1 + b1) (fp16 out)
    gemm_fp16<1, true, false, true><<<dim3(DFF / 128, BT / 128), 128, GEMM_SMEM_BYTES>>>(
        ln, wt + WT_W1, b1, nullptr, h1, BT, DFF, C);

    // 7) out = out + h1 @ w2 + b2 (fp32 out)
    gemm_fp16<0, true, true, false><<<dim3(C / 128, BT / 128), 128, GEMM_SMEM_BYTES>>>(
        h1, wt + WT_W2, b2, out, out, BT, C, DFF);
}

// round 11
// speedup vs baseline: 3.0261x; 1.0004x over previous
#include <cuda_runtime.h>
#include <cuda_fp16.h>
#include <math.h>
#include <stdint.h>

// ---------------------------------------------------------------------------
// TransformerBlock: fp16 m16n8k16 mma.sync GEMMs (K-chunk 64, one barrier per
// chunk) + fp16 flash attention (P-in-register, ldmatrix.trans V).
// Shapes: B=4, T=2048 (BT=8192), C=1024, H=16, D=64, DFF=4096
// ---------------------------------------------------------------------------

#define BT   8192
#define C    1024
#define C3   3072
#define H    16
#define D    64
#define DFF  4096
#define T    2048
#define EPS  1e-5f

// Scratch (__device__ globals; no allocations allowed)
__device__ __half g_ln[BT * C];
__device__ __half g_qkv[BT * C3];
__device__ __half g_attn[BT * C];
__device__ __half g_h1[BT * DFF];
// fp16 TRANSPOSED weights: [N][K]
#define WT_QKV  0
#define WT_PROJ (WT_QKV + C * C3)
#define WT_W1   (WT_PROJ + C * C)
#define WT_W2   (WT_W1 + C * DFF)
#define WT_TOT  (WT_W2 + DFF * C)
__device__ __half g_wt[WT_TOT];

// ---------------------------------------------------------------------------
// Helpers
// ---------------------------------------------------------------------------
__device__ __forceinline__ uint32_t smem_u32(const void* p) {
    uint32_t a;
    asm("{ .reg .u64 t; cvta.to.shared.u64 t, %1; cvt.u32.u64 %0, t; }" : "=r"(a) : "l"(p));
    return a;
}
__device__ __forceinline__ void cp_async16(uint32_t dst, const void* src) {
    asm volatile("cp.async.ca.shared.global [%0], [%1], 16;" :: "r"(dst), "l"(src) : "memory");
}
__device__ __forceinline__ void cp_commit() {
    asm volatile("cp.async.commit_group;" ::: "memory");
}
template<int N>
__device__ __forceinline__ void cp_wait() {
    asm volatile("cp.async.wait_group %0;" :: "n"(N) : "memory");
}
__device__ __forceinline__ void ldsm_x4(uint32_t& r0, uint32_t& r1, uint32_t& r2, uint32_t& r3,
                                        uint32_t addr) {
    asm volatile("ldmatrix.sync.aligned.m8n8.x4.shared.b16 {%0,%1,%2,%3}, [%4];"
                 : "=r"(r0), "=r"(r1), "=r"(r2), "=r"(r3) : "r"(addr));
}
__device__ __forceinline__ void ldsm_x4_trans(uint32_t& r0, uint32_t& r1, uint32_t& r2, uint32_t& r3,
                                              uint32_t addr) {
    asm volatile("ldmatrix.sync.aligned.m8n8.x4.trans.shared.b16 {%0,%1,%2,%3}, [%4];"
                 : "=r"(r0), "=r"(r1), "=r"(r2), "=r"(r3) : "r"(addr));
}
__device__ __forceinline__ void mma_16n8k16(float* d, const uint32_t* a, const uint32_t* b) {
    asm volatile(
        "mma.sync.aligned.m16n8k16.row.col.f32.f16.f16.f32 "
        "{%0,%1,%2,%3}, {%4,%5,%6,%7}, {%8,%9}, {%0,%1,%2,%3};"
        : "+f"(d[0]), "+f"(d[1]), "+f"(d[2]), "+f"(d[3])
        : "r"(a[0]), "r"(a[1]), "r"(a[2]), "r"(a[3]), "r"(b[0]), "r"(b[1]));
}
__device__ __forceinline__ uint32_t pack_h2(float a, float b) {
    __half2 h = __floats2half2_rn(a, b);
    return *(uint32_t*)&h;
}
__device__ __forceinline__ float gelu_exact(float v) {
    return 0.5f * v * (1.0f + erff(v * 0.70710678118654752f));
}

// ---------------------------------------------------------------------------
// Weight transpose + fp16 convert: in fp32 [K][N] -> out fp16 [N][K]
// ---------------------------------------------------------------------------
__global__ __launch_bounds__(256) void wtr_kernel(
    const float* __restrict__ in, __half* __restrict__ out, int K, int N)
{
    __shared__ float tile[64][65];
    int n0 = blockIdx.x * 64, k0 = blockIdx.y * 64;
    int t = threadIdx.x;
    #pragma unroll
    for (int it = 0; it < 4; it++) {
        int idx = t + it * 256;
        int kr = idx >> 4;
        int nc = (idx & 15) << 2;
        float4 v = *(const float4*)(in + (size_t)(k0 + kr) * N + n0 + nc);
        tile[kr][nc] = v.x; tile[kr][nc + 1] = v.y;
        tile[kr][nc + 2] = v.z; tile[kr][nc + 3] = v.w;
    }
    __syncthreads();
    #pragma unroll
    for (int it = 0; it < 2; it++) {
        int idx = t + it * 256;
        int nr = idx >> 3;
        int kc = (idx & 7) << 3;
        __half h[8];
        #pragma unroll
        for (int i = 0; i < 8; i++) h[i] = __float2half(tile[kc + i][nr]);
        *(uint4*)(out + (size_t)(n0 + nr) * K + k0 + kc) = *(uint4*)h;
    }
}

// ---------------------------------------------------------------------------
// LayerNorm (fp32 in, fp16 out)
// ---------------------------------------------------------------------------
__global__ __launch_bounds__(256) void ln_kernel(
    const float* __restrict__ x, const float* __restrict__ g,
    const float* __restrict__ beta, __half* __restrict__ out)
{
    int row = blockIdx.x;
    int t = threadIdx.x;
    const float* xr = x + (size_t)row * C;
    float4 xv = *(const float4*)(xr + t * 4);
    float s  = xv.x + xv.y + xv.z + xv.w;
    float s2 = xv.x * xv.x + xv.y * xv.y + xv.z * xv.z + xv.w * xv.w;
    #pragma unroll
    for (int o = 16; o > 0; o >>= 1) {
        s  += __shfl_xor_sync(0xffffffffu, s,  o);
        s2 += __shfl_xor_sync(0xffffffffu, s2, o);
    }
    __shared__ float ss[8], ss2[8];
    int w = t >> 5, lane = t & 31;
    if (lane == 0) { ss[w] = s; ss2[w] = s2; }
    __syncthreads();
    if (w == 0) {
        s  = (lane < 8) ? ss[lane]  : 0.f;
        s2 = (lane < 8) ? ss2[lane] : 0.f;
        #pragma unroll
        for (int o = 4; o > 0; o >>= 1) {
            s  += __shfl_xor_sync(0xffffffffu, s,  o);
            s2 += __shfl_xor_sync(0xffffffffu, s2, o);
        }
        if (lane == 0) { ss[0] = s; ss2[0] = s2; }
    }
    __syncthreads();
    float mu  = ss[0] * (1.0f / C);
    float var = ss2[0] * (1.0f / C) - mu * mu;
    float inv = rsqrtf(var + EPS);
    float4 gv = *(const float4*)(g + t * 4);
    float4 bv = *(const float4*)(beta + t * 4);
    __half2* o = (__half2*)(out + (size_t)row * C + t * 4);
    o[0] = __floats2half2_rn((xv.x - mu) * inv * gv.x + bv.x,
                             (xv.y - mu) * inv * gv.y + bv.y);
    o[1] = __floats2half2_rn((xv.z - mu) * inv * gv.z + bv.z,
                             (xv.w - mu) * inv * gv.w + bv.w);
}

// ---------------------------------------------------------------------------
// fp16 mma.sync GEMM: D[M,N] = A[M,K] @ Bt[N,K]^T (+bias)(gelu)(+resid)
// CTA 128x128, 128 threads (4 warps 2x2), warp tile 64x64,
// K-chunk 64, 2-stage cp.async, ONE barrier per chunk, ldmatrix b16.
// Smem rows: 64 halves data, stride 72 halves (144B) -> conflict-free.
// ---------------------------------------------------------------------------
#define HSTR 72
#define TILE_BYTES (128 * HSTR * 2)      // 18432
#define STAGE_BYTES (2 * TILE_BYTES)     // 36864
#define NSTAGE 2
#define GEMM_SMEM_BYTES (NSTAGE * STAGE_BYTES)

template<int ACT, bool BIAS, bool RESID, bool OUT_HALF>
__global__ __launch_bounds__(128, 2) void gemm_fp16(
    const __half* __restrict__ A, const __half* __restrict__ Bt,
    const float* __restrict__ bias, const float* __restrict__ resid,
    void* __restrict__ CoutV, int M, int N, int K)
{
    extern __shared__ char smem[];
    int t    = threadIdx.x;
    int lane = t & 31;
    int w    = t >> 5;
    int grp  = lane >> 2;
    int tg   = lane & 3;
    int bm = blockIdx.y * 128;
    int bn = blockIdx.x * 128;
    int wm = (w >> 1) * 64;
    int wn = (w & 1) * 64;

    uint32_t smemBase = smem_u32(smem);

    int lrow = lane & 7;
    int lsel = lane >> 3;
    uint32_t a_off = (uint32_t)(((wm + lrow + (lsel & 1) * 8) * HSTR + (lsel >> 1) * 8) * 2);
    uint32_t b_off = (uint32_t)(((wn + lrow + (lsel >> 1) * 8) * HSTR + (lsel & 1) * 8) * 2)
                   + (uint32_t)TILE_BYTES;

    float acc[4][8][4];
    #pragma unroll
    for (int mi = 0; mi < 4; mi++)
        #pragma unroll
        for (int ni = 0; ni < 8; ni++)
            #pragma unroll
            for (int r = 0; r < 4; r++) acc[mi][ni][r] = 0.f;

    const int NCH = K >> 6;

    auto load_chunk = [&](int c) {
        int buf = c & 1;
        uint32_t base = smemBase + (uint32_t)(buf * STAGE_BYTES);
        int k0 = c << 6;
        #pragma unroll
        for (int it = 0; it < 8; it++) {
            int idx   = t + it * 128;
            int row   = idx >> 3;
            int col16 = idx & 7;
            uint32_t soff = (uint32_t)(row * (HSTR * 2) + col16 * 16);
            cp_async16(base + soff,
                       A + (size_t)(bm + row) * K + k0 + col16 * 8);
            cp_async16(base + (uint32_t)TILE_BYTES + soff,
                       Bt + (size_t)(bn + row) * K + k0 + col16 * 8);
        }
        cp_commit();
    };

    load_chunk(0);

    for (int c = 0; c < NCH; c++) {
        cp_wait<0>();
        __syncthreads();
        if (c + 1 < NCH) load_chunk(c + 1);

        uint32_t base = smemBase + (uint32_t)((c & 1) * STAGE_BYTES);
        uint32_t aB = base + a_off;
        uint32_t bB = base + b_off;

        #pragma unroll
        for (int ks = 0; ks < 4; ks++) {
            uint32_t kOff = (uint32_t)(ks * 32);
            uint32_t af[4][4], bf[8][2];
            #pragma unroll
            for (int mi = 0; mi < 4; mi++)
                ldsm_x4(af[mi][0], af[mi][1], af[mi][2], af[mi][3],
                        aB + kOff + (uint32_t)(mi * 16 * HSTR * 2));
            #pragma unroll
            for (int p = 0; p < 4; p++)
                ldsm_x4(bf[2*p][0], bf[2*p][1], bf[2*p+1][0], bf[2*p+1][1],
                        bB + kOff + (uint32_t)(p * 16 * HSTR * 2));
            #pragma unroll
            for (int mi = 0; mi < 4; mi++)
                #pragma unroll
                for (int ni = 0; ni < 8; ni++)
                    mma_16n8k16(acc[mi][ni], af[mi], bf[ni]);
        }
    }

    #pragma unroll
    for (int mi = 0; mi < 4; mi++) {
        #pragma unroll
        for (int half = 0; half < 2; half++) {
            int row = bm + wm + mi * 16 + grp + half * 8;
            const float* rrow = RESID ? (resid + (size_t)row * N + bn) : nullptr;
            #pragma unroll
            for (int ni = 0; ni < 8; ni++) {
                int col = wn + ni * 8 + tg * 2;
                float v0 = acc[mi][ni][half * 2 + 0];
                float v1 = acc[mi][ni][half * 2 + 1];
                if (BIAS) {
                    float2 bb = *(const float2*)(bias + bn + col);
                    v0 += bb.x; v1 += bb.y;
                }
                if (ACT == 1) { v0 = gelu_exact(v0); v1 = gelu_exact(v1); }
                if (RESID) {
                    float2 rr = *(const float2*)(rrow + col);
                    v0 += rr.x; v1 += rr.y;
                }
                if (OUT_HALF) {
                    __half* orow = (__half*)CoutV + (size_t)row * N + bn;
                    *(__half2*)(orow + col) = __floats2half2_rn(v0, v1);
                } else {
                    float* orow = (float*)CoutV + (size_t)row * N + bn;
                    *(float2*)(orow + col) = make_float2(v0, v1);
                }
            }
        }
    }
}

// ---------------------------------------------------------------------------
// Flash attention, fp16 m16n8k16 (unchanged from R10).
// ---------------------------------------------------------------------------
#define ASTR 72
#define Q_BYTES   (128 * ASTR * 2)
#define KV_BYTES  (64 * ASTR * 2)
#define AST_BYTES (2 * KV_BYTES)
#define ATTN_SMEM_BYTES (Q_BYTES + 3 * AST_BYTES)

__global__ __launch_bounds__(128, 2) void attn_mma_kernel(
    const __half* __restrict__ qkv, __half* __restrict__ out)
{
    extern __shared__ char sm[];
    uint32_t smBase = smem_u32(sm);
    __half* Qs = (__half*)sm;

    int qt = blockIdx.x, h = blockIdx.y, b = blockIdx.z;
    int t = threadIdx.x, lane = t & 31, w = t >> 5;
    int grp = lane >> 2, tg = lane & 3;
    int lrow = lane & 7, lsel = lane >> 3;

    const size_t tok0 = (size_t)b * T;
    const int NCHK = T / 64;

    {
        __half2 sc = __float2half2_rn(0.125f);
        #pragma unroll
        for (int it = 0; it < 8; it++) {
            int idx   = t + it * 128;
            int row   = idx >> 3;
            int col16 = idx & 7;
            const __half* p = qkv + (tok0 + qt * 128 + row) * C3 + h * D + col16 * 8;
            uint4 v = *(const uint4*)p;
            __half2* hv = (__half2*)&v;
            hv[0] = __hmul2(hv[0], sc);
            hv[1] = __hmul2(hv[1], sc);
            hv[2] = __hmul2(hv[2], sc);
            hv[3] = __hmul2(hv[3], sc);
            *(uint4*)(Qs + row * ASTR + col16 * 8) = v;
        }
    }

    auto stage_kv = [&](int c) {
        uint32_t base = smBase + (uint32_t)Q_BYTES + (uint32_t)((c % 3) * AST_BYTES);
        int kt = c * 64;
        #pragma unroll
        for (int it = 0; it < 4; it++) {
            int idx   = t + it * 128;
            int row   = idx >> 3;
            int col16 = idx & 7;
            uint32_t soff = (uint32_t)(row * (ASTR * 2) + col16 * 16);
            const __half* kp = qkv + (tok0 + kt + row) * C3 + C + h * D + col16 * 8;
            cp_async16(base + soff, kp);
            cp_async16(base + (uint32_t)KV_BYTES + soff, kp + C);
        }
        cp_commit();
    };

    stage_kv(0);
    stage_kv(1);
    __syncthreads();

    uint32_t aq_off = (uint32_t)(((w * 32 + lrow + (lsel & 1) * 8) * ASTR + (lsel >> 1) * 8) * 2);
    uint32_t qf[2][4][4];
    #pragma unroll
    for (int mi = 0; mi < 2; mi++)
        #pragma unroll
        for (int ks = 0; ks < 4; ks++)
            ldsm_x4(qf[mi][ks][0], qf[mi][ks][1], qf[mi][ks][2], qf[mi][ks][3],
                    smBase + aq_off + (uint32_t)(mi * 16 * ASTR * 2) + (uint32_t)(ks * 32));

    float m[2][2], l[2][2];
    float oacc[2][8][4];
    #pragma unroll
    for (int mi = 0; mi < 2; mi++) {
        m[mi][0] = m[mi][1] = -1e30f;
        l[mi][0] = l[mi][1] = 0.f;
        #pragma unroll
        for (int nt = 0; nt < 8; nt++)
            #pragma unroll
            for (int r = 0; r < 4; r++) oacc[mi][nt][r] = 0.f;
    }

    uint32_t bn_off  = (uint32_t)(((lrow + (lsel >> 1) * 8) * ASTR + (lsel & 1) * 8) * 2);
    uint32_t vtr_off = (uint32_t)(((lrow + (lsel & 1) * 8) * ASTR + (lsel >> 1) * 8) * 2);

    for (int c = 0; c < NCHK; c++) {
        if (c + 1 < NCHK) cp_wait<1>(); else cp_wait<0>();
        __syncthreads();
        if (c + 2 < NCHK) stage_kv(c + 2);

        uint32_t stBase = smBase + (uint32_t)Q_BYTES + (uint32_t)((c % 3) * AST_BYTES);
        uint32_t KsB = stBase;
        uint32_t VsB = stBase + (uint32_t)KV_BYTES;

        float sacc[2][8][4];
        #pragma unroll
        for (int mi = 0; mi < 2; mi++)
            #pragma unroll
            for (int nt = 0; nt < 8; nt++)
                #pragma unroll
                for (int r = 0; r < 4; r++) sacc[mi][nt][r] = 0.f;

        #pragma unroll
        for (int ks = 0; ks < 4; ks++) {
            uint32_t bf[8][2];
            #pragma unroll
            for (int p = 0; p < 4; p++)
                ldsm_x4(bf[2*p][0], bf[2*p][1], bf[2*p+1][0], bf[2*p+1][1],
                        KsB + bn_off + (uint32_t)(p * 16 * ASTR * 2) + (uint32_t)(ks * 32));
            #pragma unroll
            for (int mi = 0; mi < 2; mi++)
                #pragma unroll
                for (int nt = 0; nt < 8; nt++)
                    mma_16n8k16(sacc[mi][nt], qf[mi][ks], bf[nt]);
        }

        #pragma unroll
        for (int mi = 0; mi < 2; mi++) {
            float r0 = -1e30f, r1 = -1e30f;
            #pragma unroll
            for (int nt = 0; nt < 8; nt++) {
                r0 = fmaxf(r0, fmaxf(sacc[mi][nt][0], sacc[mi][nt][1]));
                r1 = fmaxf(r1, fmaxf(sacc[mi][nt][2], sacc[mi][nt][3]));
            }
            r0 = fmaxf(r0, __shfl_xor_sync(0xffffffffu, r0, 1));
            r0 = fmaxf(r0, __shfl_xor_sync(0xffffffffu, r0, 2));
            r1 = fmaxf(r1, __shfl_xor_sync(0xffffffffu, r1, 1));
            r1 = fmaxf(r1, __shfl_xor_sync(0xffffffffu, r1, 2));
            float mn0 = fmaxf(m[mi][0], r0);
            float mn1 = fmaxf(m[mi][1], r1);
            float c0 = __expf(m[mi][0] - mn0);
            float c1 = __expf(m[mi][1] - mn1);
            m[mi][0] = mn0; m[mi][1] = mn1;
            l[mi][0] *= c0; l[mi][1] *= c1;
            #pragma unroll
            for (int nt = 0; nt < 8; nt++) {
                oacc[mi][nt][0] *= c0; oacc[mi][nt][1] *= c0;
                oacc[mi][nt][2] *= c1; oacc[mi][nt][3] *= c1;
            }
            #pragma unroll
            for (int nt = 0; nt < 8; nt++) {
                float p0 = __expf(sacc[mi][nt][0] - mn0);
                float p1 = __expf(sacc[mi][nt][1] - mn0);
                float p2 = __expf(sacc[mi][nt][2] - mn1);
                float p3 = __expf(sacc[mi][nt][3] - mn1);
                l[mi][0] += p0 + p1;
                l[mi][1] += p2 + p3;
                sacc[mi][nt][0] = p0; sacc[mi][nt][1] = p1;
                sacc[mi][nt][2] = p2; sacc[mi][nt][3] = p3;
            }
        }

        #pragma unroll
        for (int ks = 0; ks < 4; ks++) {
            uint32_t bf[8][2];
            #pragma unroll
            for (int p = 0; p < 4; p++)
                ldsm_x4_trans(bf[2*p][0], bf[2*p][1], bf[2*p+1][0], bf[2*p+1][1],
                              VsB + vtr_off + (uint32_t)(ks * 16 * ASTR * 2) + (uint32_t)(p * 32));
            uint32_t af[2][4];
            #pragma unroll
            for (int mi = 0; mi < 2; mi++) {
                af[mi][0] = pack_h2(sacc[mi][2*ks][0],   sacc[mi][2*ks][1]);
                af[mi][1] = pack_h2(sacc[mi][2*ks][2],   sacc[mi][2*ks][3]);
                af[mi][2] = pack_h2(sacc[mi][2*ks+1][0], sacc[mi][2*ks+1][1]);
                af[mi][3] = pack_h2(sacc[mi][2*ks+1][2], sacc[mi][2*ks+1][3]);
            }
            #pragma unroll
            for (int mi = 0; mi < 2; mi++)
                #pragma unroll
                for (int nt = 0; nt < 8; nt++)
                    mma_16n8k16(oacc[mi][nt], af[mi], bf[nt]);
        }
    }

    #pragma unroll
    for (int mi = 0; mi < 2; mi++) {
        float l0 = l[mi][0], l1 = l[mi][1];
        l0 += __shfl_xor_sync(0xffffffffu, l0, 1);
        l0 += __shfl_xor_sync(0xffffffffu, l0, 2);
        l1 += __shfl_xor_sync(0xffffffffu, l1, 1);
        l1 += __shfl_xor_sync(0xffffffffu, l1, 2);
        float i0 = 1.f / l0, i1 = 1.f / l1;
        int rlo = qt * 128 + w * 32 + mi * 16 + grp;
        __half* olo = out + (tok0 + rlo) * C + h * D;
        __half* ohi = out + (tok0 + rlo + 8) * C + h * D;
        #pragma unroll
        for (int nt = 0; nt < 8; nt++) {
            int col = nt * 8 + tg * 2;
            *(__half2*)(olo + col) = __floats2half2_rn(oacc[mi][nt][0] * i0,
                                                       oacc[mi][nt][1] * i0);
            *(__half2*)(ohi + col) = __floats2half2_rn(oacc[mi][nt][2] * i1,
                                                       oacc[mi][nt][3] * i1);
        }
    }
}

// ---------------------------------------------------------------------------
// Launch
// ---------------------------------------------------------------------------
extern "C" void kernel_launch(void* const* d_in, const int* in_sizes, int n_in,
                              void* d_out, int out_size)
{
    const float* x      = (const float*)d_in[0];
    const float* ln1_g  = (const float*)d_in[1];
    const float* ln1_b  = (const float*)d_in[2];
    const float* ln2_g  = (const float*)d_in[3];
    const float* ln2_b  = (const float*)d_in[4];
    const float* w_qkv  = (const float*)d_in[5];
    const float* w_proj = (const float*)d_in[6];
    const float* w1     = (const float*)d_in[7];
    const float* b1     = (const float*)d_in[8];
    const float* w2     = (const float*)d_in[9];
    const float* b2     = (const float*)d_in[10];
    float* out = (float*)d_out;

    __half* ln   = nullptr;  cudaGetSymbolAddress((void**)&ln,   g_ln);
    __half* qkv  = nullptr;  cudaGetSymbolAddress((void**)&qkv,  g_qkv);
    __half* attn = nullptr;  cudaGetSymbolAddress((void**)&attn, g_attn);
    __half* h1   = nullptr;  cudaGetSymbolAddress((void**)&h1,   g_h1);
    __half* wt   = nullptr;  cudaGetSymbolAddress((void**)&wt,   g_wt);

    cudaFuncSetAttribute(gemm_fp16<0, false, false, true >, cudaFuncAttributeMaxDynamicSharedMemorySize, GEMM_SMEM_BYTES);
    cudaFuncSetAttribute(gemm_fp16<0, false, true,  false>, cudaFuncAttributeMaxDynamicSharedMemorySize, GEMM_SMEM_BYTES);
    cudaFuncSetAttribute(gemm_fp16<1, true,  false, true >, cudaFuncAttributeMaxDynamicSharedMemorySize, GEMM_SMEM_BYTES);
    cudaFuncSetAttribute(gemm_fp16<0, true,  true,  false>, cudaFuncAttributeMaxDynamicSharedMemorySize, GEMM_SMEM_BYTES);
    cudaFuncSetAttribute(attn_mma_kernel, cudaFuncAttributeMaxDynamicSharedMemorySize, ATTN_SMEM_BYTES);

    // 0) transpose + convert weights: fp32 [K][N] -> fp16 [N][K]
    wtr_kernel<<<dim3(C3 / 64, C / 64), 256>>>(w_qkv,  wt + WT_QKV,  C,   C3);
    wtr_kernel<<<dim3(C  / 64, C / 64), 256>>>(w_proj, wt + WT_PROJ, C,   C);
    wtr_kernel<<<dim3(DFF / 64, C / 64), 256>>>(w1,    wt + WT_W1,   C,   DFF);
    wtr_kernel<<<dim3(C / 64, DFF / 64), 256>>>(w2,    wt + WT_W2,   DFF, C);

    // 1) LN1(x) -> ln (fp16)
    ln_kernel<<<BT, 256>>>(x, ln1_g, ln1_b, ln);

    // 2) qkv = ln @ w_qkv (fp16 out)
    gemm_fp16<0, false, false, true><<<dim3(C3 / 128, BT / 128), 128, GEMM_SMEM_BYTES>>>(
        ln, wt + WT_QKV, nullptr, nullptr, qkv, BT, C3, C);

    // 3) attention (fp16 in/out)
    attn_mma_kernel<<<dim3(T / 128, H, 4), 128, ATTN_SMEM_BYTES>>>(qkv, attn);

    // 4) out = x + attn @ w_proj (fp32 out)
    gemm_fp16<0, false, true, false><<<dim3(C / 128, BT / 128), 128, GEMM_SMEM_BYTES>>>(
        attn, wt + WT_PROJ, nullptr, x, out, BT, C, C);

    // 5) LN2(out) -> ln (fp16)
    ln_kernel<<<BT, 256>>>(out, ln2_g, ln2_b, ln);

    // 6) h1 = gelu(ln @ w1 + b1) (fp16 out)
    gemm_fp16<1, true, false, true><<<dim3(DFF / 128, BT / 128), 128, GEMM_SMEM_BYTES>>>(
        ln, wt + WT_W1, b1, nullptr, h1, BT, DFF, C);

    // 7) out = out + h1 @ w2 + b2 (fp32 out)
    gemm_fp16<0, true, true, false><<<dim3(C / 128, BT / 128), 128, GEMM_SMEM_BYTES>>>(
        h1, wt + WT_W2, b2, out, out, BT, C, DFF);
}